// round 10
// baseline (speedup 1.0000x reference)
#include <cuda_runtime.h>
#include <math.h>
#include <stdint.h>

// ---------------- problem dims ----------------
constexpr int B_   = 16;
constexpr int NQ   = 32;
constexpr int NN   = 128;
constexpr int T_   = 352;
constexpr int D_   = 768;
constexpr int H_   = 8;
constexpr int NLAY = 6;
constexpr int FF   = 3072;
constexpr int L_   = NQ + NN + T_;   // 512
constexpr int TS   = NQ + NN;        // 160
constexpr int HD   = D_ / H_;        // 96
constexpr float NEGB = -1e9f;
constexpr int QKVS = 3 * D_;         // 2304

// ---------------- device scratch ----------------
__device__ float g_x  [B_ * L_ * D_];
__device__ float g_tmp[B_ * L_ * D_];
__device__ float g_ctx[B_ * L_ * D_];      // tf32-bit floats (attention out)
__device__ float g_qkv[B_ * L_ * 3 * D_];  // tf32-bit floats (EPI=3 epilogue)
__device__ float g_ff [B_ * L_ * FF];      // tf32-bit floats (gelu out)

// tf32 pre-converted operand copies
__device__ uint32_t g_xtf    [B_ * L_ * D_];
__device__ uint32_t g_qkvw_tf[NLAY * D_ * 3 * D_];
__device__ uint32_t g_aow_tf [NLAY * D_ * D_];
__device__ uint32_t g_ff1w_tf[NLAY * D_ * FF];
__device__ uint32_t g_ff2w_tf[NLAY * FF * D_];
__device__ uint32_t g_gpw_tf [D_ * D_];
__device__ uint32_t g_gnf_tf [B_ * NN * D_];

// ---------------- tf32 helpers ----------------
__device__ __forceinline__ uint32_t f2tf(float x) {
    uint32_t r;
    asm("cvt.rna.tf32.f32 %0, %1;" : "=r"(r) : "f"(x));
    return r;
}

__device__ __forceinline__ void mma_tf32(float c[4], const uint32_t a[4],
                                         const uint32_t b[2]) {
    asm volatile(
        "mma.sync.aligned.m16n8k8.row.col.f32.tf32.tf32.f32 "
        "{%0,%1,%2,%3}, {%4,%5,%6,%7}, {%8,%9}, {%0,%1,%2,%3};"
        : "+f"(c[0]), "+f"(c[1]), "+f"(c[2]), "+f"(c[3])
        : "r"(a[0]), "r"(a[1]), "r"(a[2]), "r"(a[3]), "r"(b[0]), "r"(b[1]));
}

// ============================================================================
// TF32 GEMM — register-staged double-buffered mainloop, re-tiled for
// occupancy: 512 threads (16 warps), 32x32 warp tiles, <=64 regs/thread
// => 2 CTAs/SM = 32 warps/SM (was 16).
// EPI: 0 = +bias fp32   1 = +bias+resid fp32   2 = gelu tf32   3 = +bias tf32
// ============================================================================
constexpr int ASTR = 20;
constexpr int BSTR = 136;

template <int EPI>
__global__ __launch_bounds__(512, 2)
void tgemm(const uint32_t* __restrict__ A, const uint32_t* __restrict__ Bm,
           const float* __restrict__ bias, const float* __restrict__ resid,
           float* __restrict__ C, int M, int N, int K, int mapGraph)
{
    __shared__ uint32_t As[2][128 * ASTR];
    __shared__ uint32_t Bs[2][16 * BSTR];

    const int tid  = threadIdx.x;
    const int br   = blockIdx.y, bc = blockIdx.x;
    const int lane = tid & 31,  wid = tid >> 5;
    const int wm = (wid >> 2) * 32;      // warp row base: 0,32,64,96
    const int wn = (wid & 3) * 32;       // warp col base: 0,32,64,96
    const int lq = lane >> 2;
    const int lr = lane & 3;

    float acc[2][4][4];
#pragma unroll
    for (int mt = 0; mt < 2; mt++)
#pragma unroll
        for (int nt = 0; nt < 4; nt++)
#pragma unroll
            for (int r = 0; r < 4; r++) acc[mt][nt][r] = 0.f;

    const int nkt = K >> 4;
    uint4 pa, pb;

    // per-thread load coords (512 threads: one uint4 each for A and B)
    const int arow = tid >> 2, acg = (tid & 3) << 2;      // A: 128 x 16
    const int brow = tid >> 5, bcg = (tid & 31) << 2;     // B: 16 x 128

    auto ldA = [&](int kt) {
        pa = *(const uint4*)(A + (size_t)(br * 128 + arow) * K + kt * 16 + acg);
    };
    auto ldB = [&](int kt) {
        pb = *(const uint4*)(Bm + (size_t)(kt * 16 + brow) * N + bc * 128 + bcg);
    };
    auto stAB = [&](int buf) {
        *(uint4*)&As[buf][arow * ASTR + acg] = pa;
        *(uint4*)&Bs[buf][brow * BSTR + bcg] = pb;
    };
    auto compute = [&](int buf) {
#pragma unroll
        for (int k8 = 0; k8 < 16; k8 += 8) {
            uint32_t af[2][4], bf[4][2];
#pragma unroll
            for (int mt = 0; mt < 2; mt++) {
                const uint32_t* p = &As[buf][(wm + mt * 16 + lq) * ASTR + k8 + lr];
                af[mt][0] = p[0];
                af[mt][1] = p[8 * ASTR];
                af[mt][2] = p[4];
                af[mt][3] = p[8 * ASTR + 4];
            }
#pragma unroll
            for (int nt = 0; nt < 4; nt++) {
                const uint32_t* p = &Bs[buf][(k8 + lr) * BSTR + wn + nt * 8 + lq];
                bf[nt][0] = p[0];
                bf[nt][1] = p[4 * BSTR];
            }
#pragma unroll
            for (int mt = 0; mt < 2; mt++)
#pragma unroll
                for (int nt = 0; nt < 4; nt++)
                    mma_tf32(acc[mt][nt], af[mt], bf[nt]);
        }
    };

    ldA(0); ldB(0);
    stAB(0);
    __syncthreads();
    for (int kt = 0; kt < nkt; kt++) {
        int buf = kt & 1;
        bool more = (kt + 1 < nkt);
        if (more) { ldA(kt + 1); ldB(kt + 1); }
        compute(buf);
        if (more) stAB(buf ^ 1);
        __syncthreads();
    }

    // ---- epilogue ----
#pragma unroll
    for (int mt = 0; mt < 2; mt++) {
        int rbase = br * 128 + wm + mt * 16 + lq;
#pragma unroll
        for (int nt = 0; nt < 4; nt++) {
            int col = bc * 128 + wn + nt * 8 + lr * 2;
            float b0 = bias[col], b1 = bias[col + 1];
#pragma unroll
            for (int hh = 0; hh < 2; hh++) {
                int row = rbase + hh * 8;
                int orow = mapGraph ? (row / NN) * L_ + NQ + (row % NN) : row;
                float v0 = acc[mt][nt][hh * 2 + 0] + b0;
                float v1 = acc[mt][nt][hh * 2 + 1] + b1;
                if (EPI == 1) {
                    v0 += resid[(size_t)row * N + col];
                    v1 += resid[(size_t)row * N + col + 1];
                }
                if (EPI == 2) {
                    v0 = 0.5f * v0 * (1.0f + erff(v0 * 0.7071067811865475f));
                    v1 = 0.5f * v1 * (1.0f + erff(v1 * 0.7071067811865475f));
                }
                if (EPI == 2 || EPI == 3) {   // consumed as tf32 downstream
                    v0 = __uint_as_float(f2tf(v0));
                    v1 = __uint_as_float(f2tf(v1));
                }
                float2 o = make_float2(v0, v1);
                *(float2*)(C + (size_t)orow * N + col) = o;
            }
        }
    }
}

// ============================================================================
// tf32 conversion pass (weights / inputs); n multiple of 4
// ============================================================================
__global__ void cvt_tf(const float* __restrict__ in, uint32_t* __restrict__ out,
                       int n)
{
    int i = (blockIdx.x * blockDim.x + threadIdx.x) * 4;
    if (i >= n) return;
    float4 v = *(const float4*)(in + i);
    uint4 o = make_uint4(f2tf(v.x), f2tf(v.y), f2tf(v.z), f2tf(v.w));
    *(uint4*)(out + i) = o;
}

// ============================================================================
// Row LayerNorm (D=768), warp-shuffle reductions; dual fp32 + tf32 output
// ============================================================================
__global__ __launch_bounds__(256)
void ln_kernel(const float* __restrict__ in, float* __restrict__ out,
               uint32_t* __restrict__ out_tf,
               const float* __restrict__ g, const float* __restrict__ bta,
               const float* __restrict__ pos, const float* __restrict__ tok)
{
    const int row = blockIdx.x;
    const int l = row % L_;
    const int tid = threadIdx.x;
    const int lane = tid & 31, wid = tid >> 5;
    const float* ip = in + (size_t)row * D_;

    float v[3];
    float s = 0.f;
#pragma unroll
    for (int i = 0; i < 3; i++) {
        int d = tid + i * 256;
        float x = ip[d];
        if (pos) x += pos[l * D_ + d] + tok[d];
        v[i] = x;
        s += x;
    }
#pragma unroll
    for (int o = 16; o > 0; o >>= 1) s += __shfl_xor_sync(0xffffffffu, s, o);

    __shared__ float red[8];
    __shared__ float smean, sinv;
    if (lane == 0) red[wid] = s;
    __syncthreads();
    if (tid == 0) {
        float t = 0.f;
#pragma unroll
        for (int j = 0; j < 8; j++) t += red[j];
        smean = t * (1.0f / 768.0f);
    }
    __syncthreads();
    float mean = smean;

    float ss = 0.f;
#pragma unroll
    for (int i = 0; i < 3; i++) {
        float d0 = v[i] - mean;
        ss += d0 * d0;
    }
#pragma unroll
    for (int o = 16; o > 0; o >>= 1) ss += __shfl_xor_sync(0xffffffffu, ss, o);
    if (lane == 0) red[wid] = ss;
    __syncthreads();
    if (tid == 0) {
        float t = 0.f;
#pragma unroll
        for (int j = 0; j < 8; j++) t += red[j];
        sinv = rsqrtf(t * (1.0f / 768.0f) + 1e-12f);
    }
    __syncthreads();
    float inv = sinv;

    float* op = out + (size_t)row * D_;
    uint32_t* ot = out_tf + (size_t)row * D_;
#pragma unroll
    for (int i = 0; i < 3; i++) {
        int d = tid + i * 256;
        float y = (v[i] - mean) * inv * g[d] + bta[d];
        op[d] = y;
        ot[d] = f2tf(y);
    }
}

// ============================================================================
// TF32 tensor-core attention (unchanged from R8; qkv carries tf32 bits)
// ============================================================================
constexpr int KVW = 104;
constexpr int SW2 = 520;
constexpr int ATTN_SMEM = (64 * KVW * 3 + 64 * SW2) * 4 + L_ * 4;

__global__ __launch_bounds__(256)
void attn_mma(const uint32_t* __restrict__ qkv, float* __restrict__ ctx,
              const int* __restrict__ text_atts, const int* __restrict__ graph_mask)
{
    const int bh = blockIdx.x;
    const int b = bh / H_, h = bh % H_;
    const int qt = blockIdx.y;
    const int tid = threadIdx.x;
    const int lane = tid & 31, wid = tid >> 5;
    const int lq = lane >> 2, lr = lane & 3;

    extern __shared__ uint32_t smu[];
    uint32_t* Qs  = smu;
    uint32_t* KVb = Qs + 64 * KVW;
    uint32_t* Sb  = KVb + 2 * 64 * KVW;
    int* keep = (int*)(Sb + 64 * SW2);

    for (int j = tid; j < L_; j += 256)
        keep[j] = (j < NQ) ? 1
                : (j < TS) ? graph_mask[b * NN + (j - NQ)]
                           : text_atts[b * T_ + (j - TS)];

    const uint32_t* qbase = qkv + (size_t)(b * L_ + qt * 64) * QKVS + h * HD;
#pragma unroll
    for (int i = 0; i < 6; i++) {
        int e = tid + i * 256;
        int r = e / 24, c4 = (e % 24) * 4;
        *(uint4*)&Qs[r * KVW + c4] = *(const uint4*)(qbase + (size_t)r * QKVS + c4);
    }

    const int wm  = (wid >> 1) * 16;
    const int wnS = (wid & 1) * 32;
    const int wnV = (wid & 1) * 48;
    const float scale = 0.10206207261596577f;

    uint4 pre[6];
    auto ldKV = [&](int kc, int which) {
        const uint32_t* base = qkv + (size_t)(b * L_ + kc * 64) * QKVS + which * D_ + h * HD;
#pragma unroll
        for (int i = 0; i < 6; i++) {
            int e = tid + i * 256;
            int r = e / 24, c4 = (e % 24) * 4;
            pre[i] = *(const uint4*)(base + (size_t)r * QKVS + c4);
        }
    };
    auto stKV = [&](int buf) {
        uint32_t* KV = KVb + buf * 64 * KVW;
#pragma unroll
        for (int i = 0; i < 6; i++) {
            int e = tid + i * 256;
            int r = e / 24, c4 = (e % 24) * 4;
            *(uint4*)&KV[r * KVW + c4] = pre[i];
        }
    };

    ldKV(0, 1);
    stKV(0);
    __syncthreads();
    for (int kc = 0; kc < 8; kc++) {
        if (kc < 7) ldKV(kc + 1, 1);

        const uint32_t* KV = KVb + (kc & 1) * 64 * KVW;
        float sacc[4][4];
#pragma unroll
        for (int nt = 0; nt < 4; nt++)
#pragma unroll
            for (int r = 0; r < 4; r++) sacc[nt][r] = 0.f;

#pragma unroll
        for (int k8 = 0; k8 < 96; k8 += 8) {
            uint32_t af[4];
            const uint32_t* qp = &Qs[(wm + lq) * KVW + k8 + lr];
            af[0] = qp[0];
            af[1] = qp[8 * KVW];
            af[2] = qp[4];
            af[3] = qp[8 * KVW + 4];
#pragma unroll
            for (int nt = 0; nt < 4; nt++) {
                const uint32_t* kp = &KV[(wnS + nt * 8 + lq) * KVW + k8 + lr];
                uint32_t bf[2] = {kp[0], kp[4]};
                mma_tf32(sacc[nt], af, bf);
            }
        }

        if (kc < 7) stKV((kc + 1) & 1);

        float* Sf = (float*)Sb;
#pragma unroll
        for (int nt = 0; nt < 4; nt++) {
            int kg = kc * 64 + wnS + nt * 8 + 2 * lr;
            bool k0 = keep[kg] != 0, k1 = keep[kg + 1] != 0;
#pragma unroll
            for (int half = 0; half < 2; half++) {
                int qrow = wm + lq + half * 8;
                int qg = qt * 64 + qrow;
                bool qok = keep[qg] != 0;
                bool ok0 = qok && k0, ok1 = qok && k1;
                if (qg < TS) {
                    if (kg     >= TS) ok0 = false;
                    if (kg + 1 >= TS) ok1 = false;
                } else {
                    if (kg     >= TS && qg < kg)     ok0 = false;
                    if (kg + 1 >= TS && qg < kg + 1) ok1 = false;
                }
                float v0 = sacc[nt][half * 2 + 0] * scale + (ok0 ? 0.f : NEGB);
                float v1 = sacc[nt][half * 2 + 1] * scale + (ok1 ? 0.f : NEGB);
                *(float2*)&Sf[qrow * SW2 + kg] = make_float2(v0, v1);
            }
        }
        __syncthreads();
    }

    ldKV(0, 2);
    {
        int r = tid >> 2, p = tid & 3;
        float* row = (float*)Sb + r * SW2 + p * 128;
        float m = -INFINITY;
#pragma unroll 4
        for (int k = 0; k < 128; k++) m = fmaxf(m, row[k]);
        m = fmaxf(m, __shfl_xor_sync(0xffffffffu, m, 1));
        m = fmaxf(m, __shfl_xor_sync(0xffffffffu, m, 2));
        float sum = 0.f;
#pragma unroll 4
        for (int k = 0; k < 128; k++) {
            float e = __expf(row[k] - m);
            row[k] = e;
            sum += e;
        }
        sum += __shfl_xor_sync(0xffffffffu, sum, 1);
        sum += __shfl_xor_sync(0xffffffffu, sum, 2);
        float inv = 1.f / sum;
        uint32_t* rowb = Sb + r * SW2 + p * 128;
#pragma unroll 4
        for (int k = 0; k < 128; k++) rowb[k] = f2tf(row[k] * inv);
    }
    stKV(0);
    __syncthreads();

    float oacc[6][4];
#pragma unroll
    for (int nt = 0; nt < 6; nt++)
#pragma unroll
        for (int r = 0; r < 4; r++) oacc[nt][r] = 0.f;

    for (int kc = 0; kc < 8; kc++) {
        if (kc < 7) ldKV(kc + 1, 2);

        const uint32_t* KV = KVb + (kc & 1) * 64 * KVW;
#pragma unroll
        for (int k8 = 0; k8 < 64; k8 += 8) {
            uint32_t af[4];
            const uint32_t* pp = &Sb[(wm + lq) * SW2 + kc * 64 + k8 + lr];
            af[0] = pp[0];
            af[1] = pp[8 * SW2];
            af[2] = pp[4];
            af[3] = pp[8 * SW2 + 4];
#pragma unroll
            for (int nt = 0; nt < 6; nt++) {
                const uint32_t* vp = &KV[(k8 + lr) * KVW + wnV + nt * 8 + lq];
                uint32_t bf[2] = {vp[0], vp[4 * KVW]};
                mma_tf32(oacc[nt], af, bf);
            }
        }

        if (kc < 7) {
            stKV((kc + 1) & 1);
            __syncthreads();
        }
    }

#pragma unroll
    for (int nt = 0; nt < 6; nt++) {
#pragma unroll
        for (int half = 0; half < 2; half++) {
            int qrow = qt * 64 + wm + lq + half * 8;
            int col = h * HD + wnV + nt * 8 + 2 * lr;
            float2 o = make_float2(__uint_as_float(f2tf(oacc[nt][half * 2 + 0])),
                                   __uint_as_float(f2tf(oacc[nt][half * 2 + 1])));
            *(float2*)(ctx + (size_t)(b * L_ + qrow) * D_ + col) = o;
        }
    }
}

// ============================================================================
// misc elementwise
// ============================================================================
__global__ void fill_embed(const float* __restrict__ qtok,
                           const float* __restrict__ temb,
                           float* __restrict__ out)
{
    int idx = blockIdx.x * blockDim.x + threadIdx.x;
    if (idx >= B_ * L_ * D_) return;
    int rem = idx % (L_ * D_);
    int b = idx / (L_ * D_);
    int l = rem / D_, d = rem % D_;
    if (l < NQ)
        out[idx] = qtok[l * D_ + d];
    else if (l >= TS)
        out[idx] = temb[(size_t)(b * T_ + (l - TS)) * D_ + d];
}

__global__ void copy_out(const float* __restrict__ x, float* __restrict__ out, int n)
{
    int idx = blockIdx.x * blockDim.x + threadIdx.x;
    if (idx >= n) return;
    int rem = idx % (T_ * D_);
    int b = idx / (T_ * D_);
    int t = rem / D_, d = rem % D_;
    out[idx] = x[(size_t)(b * L_ + TS + t) * D_ + d];
}

// ============================================================================
// launcher
// ============================================================================
extern "C" void kernel_launch(void* const* d_in, const int* in_sizes, int n_in,
                              void* d_out, int out_size)
{
    const float* gnf     = (const float*)d_in[0];
    const float* temb    = (const float*)d_in[1];
    const int*   tatt    = (const int*)  d_in[2];
    const int*   gmask   = (const int*)  d_in[3];
    const float* qtok    = (const float*)d_in[4];
    const float* gproj_w = (const float*)d_in[5];
    const float* gproj_b = (const float*)d_in[6];
    const float* pos     = (const float*)d_in[7];
    const float* tok     = (const float*)d_in[8];
    const float* elng    = (const float*)d_in[9];
    const float* elnb    = (const float*)d_in[10];
    const float* qkvw    = (const float*)d_in[11];
    const float* qkvb    = (const float*)d_in[12];
    const float* aow     = (const float*)d_in[13];
    const float* aob     = (const float*)d_in[14];
    const float* ln1g    = (const float*)d_in[15];
    const float* ln1b    = (const float*)d_in[16];
    const float* ff1w    = (const float*)d_in[17];
    const float* ff1b    = (const float*)d_in[18];
    const float* ff2w    = (const float*)d_in[19];
    const float* ff2b    = (const float*)d_in[20];
    const float* ln2g    = (const float*)d_in[21];
    const float* ln2b    = (const float*)d_in[22];

    float *px, *ptmp, *pctx, *pqkv, *pff;
    uint32_t *pxtf, *pqkvwt, *paowt, *pff1wt, *pff2wt, *pgpwt, *pgnft;
    cudaGetSymbolAddress((void**)&px,    g_x);
    cudaGetSymbolAddress((void**)&ptmp,  g_tmp);
    cudaGetSymbolAddress((void**)&pctx,  g_ctx);
    cudaGetSymbolAddress((void**)&pqkv,  g_qkv);
    cudaGetSymbolAddress((void**)&pff,   g_ff);
    cudaGetSymbolAddress((void**)&pxtf,  g_xtf);
    cudaGetSymbolAddress((void**)&pqkvwt, g_qkvw_tf);
    cudaGetSymbolAddress((void**)&paowt,  g_aow_tf);
    cudaGetSymbolAddress((void**)&pff1wt, g_ff1w_tf);
    cudaGetSymbolAddress((void**)&pff2wt, g_ff2w_tf);
    cudaGetSymbolAddress((void**)&pgpwt,  g_gpw_tf);
    cudaGetSymbolAddress((void**)&pgnft,  g_gnf_tf);

    cudaFuncSetAttribute(attn_mma, cudaFuncAttributeMaxDynamicSharedMemorySize,
                         ATTN_SMEM);

    const int NROWS = B_ * L_;   // 8192

    // ---- pre-convert weights + graph features to tf32 (RNA) ----
    auto cvt = [](const float* in, uint32_t* out, int n) {
        cvt_tf<<<(n / 4 + 255) / 256, 256>>>(in, out, n);
    };
    cvt(qkvw,    pqkvwt, NLAY * D_ * 3 * D_);
    cvt(aow,     paowt,  NLAY * D_ * D_);
    cvt(ff1w,    pff1wt, NLAY * D_ * FF);
    cvt(ff2w,    pff2wt, NLAY * FF * D_);
    cvt(gproj_w, pgpwt,  D_ * D_);
    cvt(gnf,     pgnft,  B_ * NN * D_);

    // ---- embeddings ----
    fill_embed<<<(B_ * L_ * D_ + 255) / 256, 256>>>(qtok, temb, ptmp);
    tgemm<0><<<dim3(D_ / 128, (B_ * NN) / 128), 512>>>(
        pgnft, pgpwt, gproj_b, nullptr, ptmp, B_ * NN, D_, D_, 1);
    ln_kernel<<<NROWS, 256>>>(ptmp, px, pxtf, elng, elnb, pos, tok);

    // ---- 6 encoder layers ----
    for (int i = 0; i < NLAY; i++) {
        // qkv projection — EPI=3 writes tf32 bits for the attention kernel
        tgemm<3><<<dim3((3 * D_) / 128, NROWS / 128), 512>>>(
            pxtf, pqkvwt + (size_t)i * D_ * 3 * D_,
            qkvb + (size_t)i * 3 * D_, nullptr, pqkv, NROWS, 3 * D_, D_, 0);

        attn_mma<<<dim3(B_ * H_, L_ / 64), 256, ATTN_SMEM>>>(
            (const uint32_t*)pqkv, pctx, tatt, gmask);

        tgemm<1><<<dim3(D_ / 128, NROWS / 128), 512>>>(
            (const uint32_t*)pctx, paowt + (size_t)i * D_ * D_,
            aob + (size_t)i * D_, px, ptmp, NROWS, D_, D_, 0);
        ln_kernel<<<NROWS, 256>>>(ptmp, px, pxtf, ln1g + (size_t)i * D_,
                                  ln1b + (size_t)i * D_, nullptr, nullptr);

        tgemm<2><<<dim3(FF / 128, NROWS / 128), 512>>>(
            pxtf, pff1wt + (size_t)i * D_ * FF,
            ff1b + (size_t)i * FF, nullptr, pff, NROWS, FF, D_, 0);

        tgemm<1><<<dim3(D_ / 128, NROWS / 128), 512>>>(
            (const uint32_t*)pff, pff2wt + (size_t)i * FF * D_,
            ff2b + (size_t)i * D_, px, ptmp, NROWS, D_, FF, 0);
        ln_kernel<<<NROWS, 256>>>(ptmp, px, pxtf, ln2g + (size_t)i * D_,
                                  ln2b + (size_t)i * D_, nullptr, nullptr);
    }

    // ---- output: text rows ----
    copy_out<<<(out_size + 255) / 256, 256>>>(px, (float*)d_out, out_size);
}

// round 12
// speedup vs baseline: 1.6082x; 1.6082x over previous
#include <cuda_runtime.h>
#include <cuda_fp16.h>
#include <math.h>
#include <stdint.h>

// ---------------- problem dims ----------------
constexpr int B_   = 16;
constexpr int NQ   = 32;
constexpr int NN   = 128;
constexpr int T_   = 352;
constexpr int D_   = 768;
constexpr int H_   = 8;
constexpr int NLAY = 6;
constexpr int FF   = 3072;
constexpr int L_   = NQ + NN + T_;   // 512
constexpr int TS   = NQ + NN;        // 160
constexpr int HD   = D_ / H_;        // 96
constexpr float NEGB = -1e9f;
constexpr int QKVS = 3 * D_;         // 2304

// ---------------- device scratch ----------------
__device__ float g_x  [B_ * L_ * D_];          // residual stream (fp32)
__device__ float g_tmp[B_ * L_ * D_];          // pre-LN buffer (fp32)
__device__ float g_qkv[B_ * L_ * 3 * D_];      // tf32-bit floats (attention input)

// fp16 packed (half2 along K) activation operands
__device__ uint32_t g_xh  [B_ * L_ * D_ / 2];  // LN out
__device__ uint32_t g_ctxh[B_ * L_ * D_ / 2];  // attention out
__device__ uint32_t g_ffh [B_ * L_ * FF / 2];  // gelu out

// fp16 packed weights: [K/2][N] words, word(kp,n) = half2(W[2kp][n], W[2kp+1][n])
__device__ uint32_t g_qkvw_h[NLAY * D_ / 2 * 3 * D_];
__device__ uint32_t g_aow_h [NLAY * D_ / 2 * D_];
__device__ uint32_t g_ff1w_h[NLAY * D_ / 2 * FF];
__device__ uint32_t g_ff2w_h[NLAY * FF / 2 * D_];
__device__ uint32_t g_gpw_h [D_ / 2 * D_];
__device__ uint32_t g_gnf_h [B_ * NN * D_ / 2];

// ---------------- helpers ----------------
__device__ __forceinline__ uint32_t f2tf(float x) {
    uint32_t r;
    asm("cvt.rna.tf32.f32 %0, %1;" : "=r"(r) : "f"(x));
    return r;
}

__device__ __forceinline__ uint32_t pack_h2(float lo, float hi) {
    __half2 h = __floats2half2_rn(lo, hi);
    return *reinterpret_cast<uint32_t*>(&h);
}

__device__ __forceinline__ void mma_tf32(float c[4], const uint32_t a[4],
                                         const uint32_t b[2]) {
    asm volatile(
        "mma.sync.aligned.m16n8k8.row.col.f32.tf32.tf32.f32 "
        "{%0,%1,%2,%3}, {%4,%5,%6,%7}, {%8,%9}, {%0,%1,%2,%3};"
        : "+f"(c[0]), "+f"(c[1]), "+f"(c[2]), "+f"(c[3])
        : "r"(a[0]), "r"(a[1]), "r"(a[2]), "r"(a[3]), "r"(b[0]), "r"(b[1]));
}

__device__ __forceinline__ void mma_f16(float c[4], const uint32_t a[4],
                                        const uint32_t b[2]) {
    asm volatile(
        "mma.sync.aligned.m16n8k16.row.col.f32.f16.f16.f32 "
        "{%0,%1,%2,%3}, {%4,%5,%6,%7}, {%8,%9}, {%0,%1,%2,%3};"
        : "+f"(c[0]), "+f"(c[1]), "+f"(c[2]), "+f"(c[3])
        : "r"(a[0]), "r"(a[1]), "r"(a[2]), "r"(a[3]), "r"(b[0]), "r"(b[1]));
}

// ============================================================================
// FP16 GEMM — R8's proven register-staged double-buffered structure, word-level
// identical addressing; each word = half2 (2 K-elements), K-tile = 32 K.
// A: [M, K/2] words.  B: [K/2, N] words.  Accumulate fp32.
// EPI: 0 = +bias fp32   1 = +bias+resid fp32   2 = gelu -> half2 packed
//      3 = +bias -> tf32-bit fp32 (attention input)
// ============================================================================
constexpr int ASTR = 20;
constexpr int BSTR = 136;

template <int EPI>
__global__ __launch_bounds__(256)
void hgemm(const uint32_t* __restrict__ A, const uint32_t* __restrict__ Bm,
           const float* __restrict__ bias, const float* __restrict__ resid,
           float* __restrict__ C, int M, int N, int K, int mapGraph)
{
    __shared__ uint32_t As[2][128 * ASTR];
    __shared__ uint32_t Bs[2][16 * BSTR];

    const int tid  = threadIdx.x;
    const int br   = blockIdx.y, bc = blockIdx.x;
    const int lane = tid & 31,  wid = tid >> 5;
    const int wm = (wid >> 2) * 64;
    const int wn = (wid & 3) * 32;
    const int lq = lane >> 2;
    const int lr = lane & 3;

    float acc[4][4][4];
#pragma unroll
    for (int mt = 0; mt < 4; mt++)
#pragma unroll
        for (int nt = 0; nt < 4; nt++)
#pragma unroll
            for (int r = 0; r < 4; r++) acc[mt][nt][r] = 0.f;

    const int Kw  = K >> 1;          // words per A row
    const int nkt = K >> 5;          // 32 K-elements (16 words) per tile
    uint4 pa[2], pb[2];

    auto ldA = [&](int kt) {
#pragma unroll
        for (int i = 0; i < 2; i++) {
            int id  = tid + i * 256;
            int row = id >> 2, cg = (id & 3) << 2;
            pa[i] = *(const uint4*)(A + (size_t)(br * 128 + row) * Kw + kt * 16 + cg);
        }
    };
    auto ldB = [&](int kt) {
#pragma unroll
        for (int i = 0; i < 2; i++) {
            int id  = tid + i * 256;
            int row = id >> 5, cg = (id & 31) << 2;
            pb[i] = *(const uint4*)(Bm + (size_t)(kt * 16 + row) * N + bc * 128 + cg);
        }
    };
    auto stAB = [&](int buf) {
#pragma unroll
        for (int i = 0; i < 2; i++) {
            int id  = tid + i * 256;
            int row = id >> 2, cg = (id & 3) << 2;
            *(uint4*)&As[buf][row * ASTR + cg] = pa[i];
        }
#pragma unroll
        for (int i = 0; i < 2; i++) {
            int id  = tid + i * 256;
            int row = id >> 5, cg = (id & 31) << 2;
            *(uint4*)&Bs[buf][row * BSTR + cg] = pb[i];
        }
    };
    auto compute = [&](int buf) {
#pragma unroll
        for (int k8 = 0; k8 < 16; k8 += 8) {     // k8 = word offset (8 words = 16 K)
            uint32_t af[4][4], bf[4][2];
#pragma unroll
            for (int mt = 0; mt < 4; mt++) {
                const uint32_t* p = &As[buf][(wm + mt * 16 + lq) * ASTR + k8 + lr];
                af[mt][0] = p[0];
                af[mt][1] = p[8 * ASTR];
                af[mt][2] = p[4];
                af[mt][3] = p[8 * ASTR + 4];
            }
#pragma unroll
            for (int nt = 0; nt < 4; nt++) {
                const uint32_t* p = &Bs[buf][(k8 + lr) * BSTR + wn + nt * 8 + lq];
                bf[nt][0] = p[0];
                bf[nt][1] = p[4 * BSTR];
            }
#pragma unroll
            for (int mt = 0; mt < 4; mt++)
#pragma unroll
                for (int nt = 0; nt < 4; nt++)
                    mma_f16(acc[mt][nt], af[mt], bf[nt]);
        }
    };

    ldA(0); ldB(0);
    stAB(0);
    __syncthreads();
    for (int kt = 0; kt < nkt; kt++) {
        int buf = kt & 1;
        bool more = (kt + 1 < nkt);
        if (more) { ldA(kt + 1); ldB(kt + 1); }
        compute(buf);
        if (more) stAB(buf ^ 1);
        __syncthreads();
    }

    // ---- epilogue ----
#pragma unroll
    for (int mt = 0; mt < 4; mt++) {
        int rbase = br * 128 + wm + mt * 16 + lq;
#pragma unroll
        for (int nt = 0; nt < 4; nt++) {
            int col = bc * 128 + wn + nt * 8 + lr * 2;
            float b0 = bias[col], b1 = bias[col + 1];
#pragma unroll
            for (int hh = 0; hh < 2; hh++) {
                int row = rbase + hh * 8;
                int orow = mapGraph ? (row / NN) * L_ + NQ + (row % NN) : row;
                float v0 = acc[mt][nt][hh * 2 + 0] + b0;
                float v1 = acc[mt][nt][hh * 2 + 1] + b1;
                if (EPI == 1) {
                    v0 += resid[(size_t)row * N + col];
                    v1 += resid[(size_t)row * N + col + 1];
                }
                if (EPI == 2) {
                    v0 = 0.5f * v0 * (1.0f + erff(v0 * 0.7071067811865475f));
                    v1 = 0.5f * v1 * (1.0f + erff(v1 * 0.7071067811865475f));
                    ((uint32_t*)C)[(size_t)orow * (N >> 1) + (col >> 1)] =
                        pack_h2(v0, v1);
                } else if (EPI == 3) {
                    v0 = __uint_as_float(f2tf(v0));
                    v1 = __uint_as_float(f2tf(v1));
                    *(float2*)(C + (size_t)orow * N + col) = make_float2(v0, v1);
                } else {
                    *(float2*)(C + (size_t)orow * N + col) = make_float2(v0, v1);
                }
            }
        }
    }
}

// ============================================================================
// conversion passes
// ============================================================================
// contiguous fp32 -> half2-packed words (A-side arrays); nwords even
__global__ void cvt_h(const float* __restrict__ in, uint32_t* __restrict__ out,
                      int nwords)
{
    int w = (blockIdx.x * blockDim.x + threadIdx.x) * 2;
    if (w >= nwords) return;
    float4 v = *(const float4*)(in + 2 * w);
    *(uint2*)(out + w) = make_uint2(pack_h2(v.x, v.y), pack_h2(v.z, v.w));
}

// weights [K][N] fp32 -> [K/2][N] half2-packed-along-K; blockIdx.z = layer
__global__ void cvt_wh(const float* __restrict__ in, uint32_t* __restrict__ out,
                       int K, int N)
{
    const float* ip = in + (size_t)blockIdx.z * K * N;
    uint32_t* op = out + (size_t)blockIdx.z * (K / 2) * N;
    int idx = blockIdx.x * blockDim.x + threadIdx.x;
    int total = (K >> 1) * (N >> 2);
    if (idx >= total) return;
    int kp = idx / (N >> 2), ng = (idx % (N >> 2)) * 4;
    const float* r0 = ip + (size_t)(2 * kp) * N + ng;
    float4 a = *(const float4*)r0;
    float4 b = *(const float4*)(r0 + N);
    *(uint4*)(op + (size_t)kp * N + ng) =
        make_uint4(pack_h2(a.x, b.x), pack_h2(a.y, b.y),
                   pack_h2(a.z, b.z), pack_h2(a.w, b.w));
}

// ============================================================================
// Row LayerNorm (D=768); dual fp32 + fp16 output
// ============================================================================
__global__ __launch_bounds__(256)
void ln_kernel(const float* __restrict__ in, float* __restrict__ out,
               uint32_t* __restrict__ out_h,
               const float* __restrict__ g, const float* __restrict__ bta,
               const float* __restrict__ pos, const float* __restrict__ tok)
{
    const int row = blockIdx.x;
    const int l = row % L_;
    const int tid = threadIdx.x;
    const int lane = tid & 31, wid = tid >> 5;
    const float* ip = in + (size_t)row * D_;

    float v[3];
    float s = 0.f;
#pragma unroll
    for (int i = 0; i < 3; i++) {
        int d = tid + i * 256;
        float x = ip[d];
        if (pos) x += pos[l * D_ + d] + tok[d];
        v[i] = x;
        s += x;
    }
#pragma unroll
    for (int o = 16; o > 0; o >>= 1) s += __shfl_xor_sync(0xffffffffu, s, o);

    __shared__ float red[8];
    __shared__ float smean, sinv;
    if (lane == 0) red[wid] = s;
    __syncthreads();
    if (tid == 0) {
        float t = 0.f;
#pragma unroll
        for (int j = 0; j < 8; j++) t += red[j];
        smean = t * (1.0f / 768.0f);
    }
    __syncthreads();
    float mean = smean;

    float ss = 0.f;
#pragma unroll
    for (int i = 0; i < 3; i++) {
        float d0 = v[i] - mean;
        ss += d0 * d0;
    }
#pragma unroll
    for (int o = 16; o > 0; o >>= 1) ss += __shfl_xor_sync(0xffffffffu, ss, o);
    if (lane == 0) red[wid] = ss;
    __syncthreads();
    if (tid == 0) {
        float t = 0.f;
#pragma unroll
        for (int j = 0; j < 8; j++) t += red[j];
        sinv = rsqrtf(t * (1.0f / 768.0f) + 1e-12f);
    }
    __syncthreads();
    float inv = sinv;

    float* op = out + (size_t)row * D_;
    __half* oh = (__half*)(out_h + (size_t)row * (D_ / 2));
#pragma unroll
    for (int i = 0; i < 3; i++) {
        int d = tid + i * 256;
        float y = (v[i] - mean) * inv * g[d] + bta[d];
        op[d] = y;
        oh[d] = __float2half_rn(y);
    }
}

// ============================================================================
// TF32 tensor-core attention (R8 structure; qkv tf32-bit floats; ctx -> half2)
// ============================================================================
constexpr int KVW = 104;
constexpr int SW2 = 520;
constexpr int ATTN_SMEM = (64 * KVW * 3 + 64 * SW2) * 4 + L_ * 4;

__global__ __launch_bounds__(256)
void attn_mma(const uint32_t* __restrict__ qkv, uint32_t* __restrict__ ctxh,
              const int* __restrict__ text_atts, const int* __restrict__ graph_mask)
{
    const int bh = blockIdx.x;
    const int b = bh / H_, h = bh % H_;
    const int qt = blockIdx.y;
    const int tid = threadIdx.x;
    const int lane = tid & 31, wid = tid >> 5;
    const int lq = lane >> 2, lr = lane & 3;

    extern __shared__ uint32_t smu[];
    uint32_t* Qs  = smu;
    uint32_t* KVb = Qs + 64 * KVW;
    uint32_t* Sb  = KVb + 2 * 64 * KVW;
    int* keep = (int*)(Sb + 64 * SW2);

    for (int j = tid; j < L_; j += 256)
        keep[j] = (j < NQ) ? 1
                : (j < TS) ? graph_mask[b * NN + (j - NQ)]
                           : text_atts[b * T_ + (j - TS)];

    const uint32_t* qbase = qkv + (size_t)(b * L_ + qt * 64) * QKVS + h * HD;
#pragma unroll
    for (int i = 0; i < 6; i++) {
        int e = tid + i * 256;
        int r = e / 24, c4 = (e % 24) * 4;
        *(uint4*)&Qs[r * KVW + c4] = *(const uint4*)(qbase + (size_t)r * QKVS + c4);
    }

    const int wm  = (wid >> 1) * 16;
    const int wnS = (wid & 1) * 32;
    const int wnV = (wid & 1) * 48;
    const float scale = 0.10206207261596577f;

    uint4 pre[6];
    auto ldKV = [&](int kc, int which) {
        const uint32_t* base = qkv + (size_t)(b * L_ + kc * 64) * QKVS + which * D_ + h * HD;
#pragma unroll
        for (int i = 0; i < 6; i++) {
            int e = tid + i * 256;
            int r = e / 24, c4 = (e % 24) * 4;
            pre[i] = *(const uint4*)(base + (size_t)r * QKVS + c4);
        }
    };
    auto stKV = [&](int buf) {
        uint32_t* KV = KVb + buf * 64 * KVW;
#pragma unroll
        for (int i = 0; i < 6; i++) {
            int e = tid + i * 256;
            int r = e / 24, c4 = (e % 24) * 4;
            *(uint4*)&KV[r * KVW + c4] = pre[i];
        }
    };

    ldKV(0, 1);
    stKV(0);
    __syncthreads();
    for (int kc = 0; kc < 8; kc++) {
        if (kc < 7) ldKV(kc + 1, 1);

        const uint32_t* KV = KVb + (kc & 1) * 64 * KVW;
        float sacc[4][4];
#pragma unroll
        for (int nt = 0; nt < 4; nt++)
#pragma unroll
            for (int r = 0; r < 4; r++) sacc[nt][r] = 0.f;

#pragma unroll
        for (int k8 = 0; k8 < 96; k8 += 8) {
            uint32_t af[4];
            const uint32_t* qp = &Qs[(wm + lq) * KVW + k8 + lr];
            af[0] = qp[0];
            af[1] = qp[8 * KVW];
            af[2] = qp[4];
            af[3] = qp[8 * KVW + 4];
#pragma unroll
            for (int nt = 0; nt < 4; nt++) {
                const uint32_t* kp = &KV[(wnS + nt * 8 + lq) * KVW + k8 + lr];
                uint32_t bf[2] = {kp[0], kp[4]};
                mma_tf32(sacc[nt], af, bf);
            }
        }

        if (kc < 7) stKV((kc + 1) & 1);

        float* Sf = (float*)Sb;
#pragma unroll
        for (int nt = 0; nt < 4; nt++) {
            int kg = kc * 64 + wnS + nt * 8 + 2 * lr;
            bool k0 = keep[kg] != 0, k1 = keep[kg + 1] != 0;
#pragma unroll
            for (int half = 0; half < 2; half++) {
                int qrow = wm + lq + half * 8;
                int qg = qt * 64 + qrow;
                bool qok = keep[qg] != 0;
                bool ok0 = qok && k0, ok1 = qok && k1;
                if (qg < TS) {
                    if (kg     >= TS) ok0 = false;
                    if (kg + 1 >= TS) ok1 = false;
                } else {
                    if (kg     >= TS && qg < kg)     ok0 = false;
                    if (kg + 1 >= TS && qg < kg + 1) ok1 = false;
                }
                float v0 = sacc[nt][half * 2 + 0] * scale + (ok0 ? 0.f : NEGB);
                float v1 = sacc[nt][half * 2 + 1] * scale + (ok1 ? 0.f : NEGB);
                *(float2*)&Sf[qrow * SW2 + kg] = make_float2(v0, v1);
            }
        }
        __syncthreads();
    }

    ldKV(0, 2);
    {
        int r = tid >> 2, p = tid & 3;
        float* row = (float*)Sb + r * SW2 + p * 128;
        float m = -INFINITY;
#pragma unroll 4
        for (int k = 0; k < 128; k++) m = fmaxf(m, row[k]);
        m = fmaxf(m, __shfl_xor_sync(0xffffffffu, m, 1));
        m = fmaxf(m, __shfl_xor_sync(0xffffffffu, m, 2));
        float sum = 0.f;
#pragma unroll 4
        for (int k = 0; k < 128; k++) {
            float e = __expf(row[k] - m);
            row[k] = e;
            sum += e;
        }
        sum += __shfl_xor_sync(0xffffffffu, sum, 1);
        sum += __shfl_xor_sync(0xffffffffu, sum, 2);
        float inv = 1.f / sum;
        uint32_t* rowb = Sb + r * SW2 + p * 128;
#pragma unroll 4
        for (int k = 0; k < 128; k++) rowb[k] = f2tf(row[k] * inv);
    }
    stKV(0);
    __syncthreads();

    float oacc[6][4];
#pragma unroll
    for (int nt = 0; nt < 6; nt++)
#pragma unroll
        for (int r = 0; r < 4; r++) oacc[nt][r] = 0.f;

    for (int kc = 0; kc < 8; kc++) {
        if (kc < 7) ldKV(kc + 1, 2);

        const uint32_t* KV = KVb + (kc & 1) * 64 * KVW;
#pragma unroll
        for (int k8 = 0; k8 < 64; k8 += 8) {
            uint32_t af[4];
            const uint32_t* pp = &Sb[(wm + lq) * SW2 + kc * 64 + k8 + lr];
            af[0] = pp[0];
            af[1] = pp[8 * SW2];
            af[2] = pp[4];
            af[3] = pp[8 * SW2 + 4];
#pragma unroll
            for (int nt = 0; nt < 6; nt++) {
                const uint32_t* vp = &KV[(k8 + lr) * KVW + wnV + nt * 8 + lq];
                uint32_t bf[2] = {vp[0], vp[4 * KVW]};
                mma_tf32(oacc[nt], af, bf);
            }
        }

        if (kc < 7) {
            stKV((kc + 1) & 1);
            __syncthreads();
        }
    }

    // ctx -> half2 packed (A operand of the attn-out fp16 GEMM)
#pragma unroll
    for (int nt = 0; nt < 6; nt++) {
#pragma unroll
        for (int half = 0; half < 2; half++) {
            int qrow = qt * 64 + wm + lq + half * 8;
            int col = h * HD + wnV + nt * 8 + 2 * lr;   // even
            ctxh[(size_t)(b * L_ + qrow) * (D_ / 2) + (col >> 1)] =
                pack_h2(oacc[nt][half * 2 + 0], oacc[nt][half * 2 + 1]);
        }
    }
}

// ============================================================================
// misc elementwise
// ============================================================================
__global__ void fill_embed(const float* __restrict__ qtok,
                           const float* __restrict__ temb,
                           float* __restrict__ out)
{
    int idx = blockIdx.x * blockDim.x + threadIdx.x;
    if (idx >= B_ * L_ * D_) return;
    int rem = idx % (L_ * D_);
    int b = idx / (L_ * D_);
    int l = rem / D_, d = rem % D_;
    if (l < NQ)
        out[idx] = qtok[l * D_ + d];
    else if (l >= TS)
        out[idx] = temb[(size_t)(b * T_ + (l - TS)) * D_ + d];
}

__global__ void copy_out(const float* __restrict__ x, float* __restrict__ out, int n)
{
    int idx = blockIdx.x * blockDim.x + threadIdx.x;
    if (idx >= n) return;
    int rem = idx % (T_ * D_);
    int b = idx / (T_ * D_);
    int t = rem / D_, d = rem % D_;
    out[idx] = x[(size_t)(b * L_ + TS + t) * D_ + d];
}

// ============================================================================
// launcher
// ============================================================================
extern "C" void kernel_launch(void* const* d_in, const int* in_sizes, int n_in,
                              void* d_out, int out_size)
{
    const float* gnf     = (const float*)d_in[0];
    const float* temb    = (const float*)d_in[1];
    const int*   tatt    = (const int*)  d_in[2];
    const int*   gmask   = (const int*)  d_in[3];
    const float* qtok    = (const float*)d_in[4];
    const float* gproj_w = (const float*)d_in[5];
    const float* gproj_b = (const float*)d_in[6];
    const float* pos     = (const float*)d_in[7];
    const float* tok     = (const float*)d_in[8];
    const float* elng    = (const float*)d_in[9];
    const float* elnb    = (const float*)d_in[10];
    const float* qkvw    = (const float*)d_in[11];
    const float* qkvb    = (const float*)d_in[12];
    const float* aow     = (const float*)d_in[13];
    const float* aob     = (const float*)d_in[14];
    const float* ln1g    = (const float*)d_in[15];
    const float* ln1b    = (const float*)d_in[16];
    const float* ff1w    = (const float*)d_in[17];
    const float* ff1b    = (const float*)d_in[18];
    const float* ff2w    = (const float*)d_in[19];
    const float* ff2b    = (const float*)d_in[20];
    const float* ln2g    = (const float*)d_in[21];
    const float* ln2b    = (const float*)d_in[22];

    float *px, *ptmp, *pqkv;
    uint32_t *pxh, *pctxh, *pffh;
    uint32_t *pqkvwh, *paowh, *pff1wh, *pff2wh, *pgpwh, *pgnfh;
    cudaGetSymbolAddress((void**)&px,    g_x);
    cudaGetSymbolAddress((void**)&ptmp,  g_tmp);
    cudaGetSymbolAddress((void**)&pqkv,  g_qkv);
    cudaGetSymbolAddress((void**)&pxh,   g_xh);
    cudaGetSymbolAddress((void**)&pctxh, g_ctxh);
    cudaGetSymbolAddress((void**)&pffh,  g_ffh);
    cudaGetSymbolAddress((void**)&pqkvwh, g_qkvw_h);
    cudaGetSymbolAddress((void**)&paowh,  g_aow_h);
    cudaGetSymbolAddress((void**)&pff1wh, g_ff1w_h);
    cudaGetSymbolAddress((void**)&pff2wh, g_ff2w_h);
    cudaGetSymbolAddress((void**)&pgpwh,  g_gpw_h);
    cudaGetSymbolAddress((void**)&pgnfh,  g_gnf_h);

    cudaFuncSetAttribute(attn_mma, cudaFuncAttributeMaxDynamicSharedMemorySize,
                         ATTN_SMEM);

    const int NROWS = B_ * L_;   // 8192

    // ---- one-time weight packing: fp32 [K,N] -> half2 [K/2][N] ----
    auto wh = [](const float* in, uint32_t* out, int K, int N, int layers) {
        int total = (K / 2) * (N / 4);
        dim3 gr((total + 255) / 256, 1, layers);
        cvt_wh<<<gr, 256>>>(in, out, K, N);
    };
    wh(qkvw,    pqkvwh, D_, 3 * D_, NLAY);
    wh(aow,     paowh,  D_, D_,     NLAY);
    wh(ff1w,    pff1wh, D_, FF,     NLAY);
    wh(ff2w,    pff2wh, FF, D_,     NLAY);
    wh(gproj_w, pgpwh,  D_, D_,     1);
    cvt_h<<<(B_ * NN * D_ / 2 / 2 + 255) / 256, 256>>>(gnf, pgnfh, B_ * NN * D_ / 2);

    // ---- embeddings ----
    fill_embed<<<(B_ * L_ * D_ + 255) / 256, 256>>>(qtok, temb, ptmp);
    hgemm<0><<<dim3(D_ / 128, (B_ * NN) / 128), 256>>>(
        pgnfh, pgpwh, gproj_b, nullptr, ptmp, B_ * NN, D_, D_, 1);
    ln_kernel<<<NROWS, 256>>>(ptmp, px, pxh, elng, elnb, pos, tok);

    // ---- 6 encoder layers ----
    for (int i = 0; i < NLAY; i++) {
        // qkv projection — fp16 GEMM, tf32-bit fp32 output for attention
        hgemm<3><<<dim3((3 * D_) / 128, NROWS / 128), 256>>>(
            pxh, pqkvwh + (size_t)i * (D_ / 2) * 3 * D_,
            qkvb + (size_t)i * 3 * D_, nullptr, pqkv, NROWS, 3 * D_, D_, 0);

        attn_mma<<<dim3(B_ * H_, L_ / 64), 256, ATTN_SMEM>>>(
            (const uint32_t*)pqkv, pctxh, tatt, gmask);

        hgemm<1><<<dim3(D_ / 128, NROWS / 128), 256>>>(
            pctxh, paowh + (size_t)i * (D_ / 2) * D_,
            aob + (size_t)i * D_, px, ptmp, NROWS, D_, D_, 0);
        ln_kernel<<<NROWS, 256>>>(ptmp, px, pxh, ln1g + (size_t)i * D_,
                                  ln1b + (size_t)i * D_, nullptr, nullptr);

        hgemm<2><<<dim3(FF / 128, NROWS / 128), 256>>>(
            pxh, pff1wh + (size_t)i * (D_ / 2) * FF,
            ff1b + (size_t)i * FF, nullptr, (float*)pffh, NROWS, FF, D_, 0);

        hgemm<1><<<dim3(D_ / 128, NROWS / 128), 256>>>(
            pffh, pff2wh + (size_t)i * (FF / 2) * D_,
            ff2b + (size_t)i * D_, px, ptmp, NROWS, D_, FF, 0);
        ln_kernel<<<NROWS, 256>>>(ptmp, px, pxh, ln2g + (size_t)i * D_,
                                  ln2b + (size_t)i * D_, nullptr, nullptr);
    }

    // ---- output: text rows ----
    copy_out<<<(out_size + 255) / 256, 256>>>(px, (float*)d_out, out_size);
}

// round 13
// speedup vs baseline: 1.8208x; 1.1322x over previous
#include <cuda_runtime.h>
#include <cuda_fp16.h>
#include <math.h>
#include <stdint.h>

// ---------------- problem dims ----------------
constexpr int B_   = 16;
constexpr int NQ   = 32;
constexpr int NN   = 128;
constexpr int T_   = 352;
constexpr int D_   = 768;
constexpr int H_   = 8;
constexpr int NLAY = 6;
constexpr int FF   = 3072;
constexpr int L_   = NQ + NN + T_;   // 512
constexpr int TS   = NQ + NN;        // 160
constexpr int HD   = D_ / H_;        // 96
constexpr float NEGB = -1e9f;
constexpr int QKVW_ = 3 * D_ / 2;    // 1152 words per qkv row

// ---------------- device scratch ----------------
__device__ float    g_x  [B_ * L_ * D_];          // residual stream (fp32)
__device__ float    g_tmp[B_ * L_ * D_];          // pre-LN buffer (fp32)
__device__ uint32_t g_qkvh[B_ * L_ * QKVW_];      // qkv, half2 packed along channel

// fp16 packed (half2 along K) activation operands
__device__ uint32_t g_xh  [B_ * L_ * D_ / 2];
__device__ uint32_t g_ctxh[B_ * L_ * D_ / 2];
__device__ uint32_t g_ffh [B_ * L_ * FF / 2];

// fp16 packed weights: [K/2][N] words
__device__ uint32_t g_qkvw_h[NLAY * D_ / 2 * 3 * D_];
__device__ uint32_t g_aow_h [NLAY * D_ / 2 * D_];
__device__ uint32_t g_ff1w_h[NLAY * D_ / 2 * FF];
__device__ uint32_t g_ff2w_h[NLAY * FF / 2 * D_];
__device__ uint32_t g_gpw_h [D_ / 2 * D_];
__device__ uint32_t g_gnf_h [B_ * NN * D_ / 2];

// ---------------- helpers ----------------
__device__ __forceinline__ uint32_t pack_h2(float lo, float hi) {
    __half2 h = __floats2half2_rn(lo, hi);
    return *reinterpret_cast<uint32_t*>(&h);
}

__device__ __forceinline__ void mma_f16(float c[4], const uint32_t a[4],
                                        const uint32_t b[2]) {
    asm volatile(
        "mma.sync.aligned.m16n8k16.row.col.f32.f16.f16.f32 "
        "{%0,%1,%2,%3}, {%4,%5,%6,%7}, {%8,%9}, {%0,%1,%2,%3};"
        : "+f"(c[0]), "+f"(c[1]), "+f"(c[2]), "+f"(c[3])
        : "r"(a[0]), "r"(a[1]), "r"(a[2]), "r"(a[3]), "r"(b[0]), "r"(b[1]));
}

// ============================================================================
// FP16 GEMM (proven R12 structure). A: [M,K/2] words. B: [K/2,N] words.
// EPI: 0 = +bias fp32   1 = +bias+resid fp32   2 = gelu -> half2 packed
//      3 = +bias -> half2 packed (qkv for attention)
// ============================================================================
constexpr int ASTR = 20;
constexpr int BSTR = 136;

template <int EPI>
__global__ __launch_bounds__(256)
void hgemm(const uint32_t* __restrict__ A, const uint32_t* __restrict__ Bm,
           const float* __restrict__ bias, const float* __restrict__ resid,
           float* __restrict__ C, int M, int N, int K, int mapGraph)
{
    __shared__ uint32_t As[2][128 * ASTR];
    __shared__ uint32_t Bs[2][16 * BSTR];

    const int tid  = threadIdx.x;
    const int br   = blockIdx.y, bc = blockIdx.x;
    const int lane = tid & 31,  wid = tid >> 5;
    const int wm = (wid >> 2) * 64;
    const int wn = (wid & 3) * 32;
    const int lq = lane >> 2;
    const int lr = lane & 3;

    float acc[4][4][4];
#pragma unroll
    for (int mt = 0; mt < 4; mt++)
#pragma unroll
        for (int nt = 0; nt < 4; nt++)
#pragma unroll
            for (int r = 0; r < 4; r++) acc[mt][nt][r] = 0.f;

    const int Kw  = K >> 1;
    const int nkt = K >> 5;
    uint4 pa[2], pb[2];

    auto ldA = [&](int kt) {
#pragma unroll
        for (int i = 0; i < 2; i++) {
            int id  = tid + i * 256;
            int row = id >> 2, cg = (id & 3) << 2;
            pa[i] = *(const uint4*)(A + (size_t)(br * 128 + row) * Kw + kt * 16 + cg);
        }
    };
    auto ldB = [&](int kt) {
#pragma unroll
        for (int i = 0; i < 2; i++) {
            int id  = tid + i * 256;
            int row = id >> 5, cg = (id & 31) << 2;
            pb[i] = *(const uint4*)(Bm + (size_t)(kt * 16 + row) * N + bc * 128 + cg);
        }
    };
    auto stAB = [&](int buf) {
#pragma unroll
        for (int i = 0; i < 2; i++) {
            int id  = tid + i * 256;
            int row = id >> 2, cg = (id & 3) << 2;
            *(uint4*)&As[buf][row * ASTR + cg] = pa[i];
        }
#pragma unroll
        for (int i = 0; i < 2; i++) {
            int id  = tid + i * 256;
            int row = id >> 5, cg = (id & 31) << 2;
            *(uint4*)&Bs[buf][row * BSTR + cg] = pb[i];
        }
    };
    auto compute = [&](int buf) {
#pragma unroll
        for (int k8 = 0; k8 < 16; k8 += 8) {
            uint32_t af[4][4], bf[4][2];
#pragma unroll
            for (int mt = 0; mt < 4; mt++) {
                const uint32_t* p = &As[buf][(wm + mt * 16 + lq) * ASTR + k8 + lr];
                af[mt][0] = p[0];
                af[mt][1] = p[8 * ASTR];
                af[mt][2] = p[4];
                af[mt][3] = p[8 * ASTR + 4];
            }
#pragma unroll
            for (int nt = 0; nt < 4; nt++) {
                const uint32_t* p = &Bs[buf][(k8 + lr) * BSTR + wn + nt * 8 + lq];
                bf[nt][0] = p[0];
                bf[nt][1] = p[4 * BSTR];
            }
#pragma unroll
            for (int mt = 0; mt < 4; mt++)
#pragma unroll
                for (int nt = 0; nt < 4; nt++)
                    mma_f16(acc[mt][nt], af[mt], bf[nt]);
        }
    };

    ldA(0); ldB(0);
    stAB(0);
    __syncthreads();
    for (int kt = 0; kt < nkt; kt++) {
        int buf = kt & 1;
        bool more = (kt + 1 < nkt);
        if (more) { ldA(kt + 1); ldB(kt + 1); }
        compute(buf);
        if (more) stAB(buf ^ 1);
        __syncthreads();
    }

    // ---- epilogue ----
#pragma unroll
    for (int mt = 0; mt < 4; mt++) {
        int rbase = br * 128 + wm + mt * 16 + lq;
#pragma unroll
        for (int nt = 0; nt < 4; nt++) {
            int col = bc * 128 + wn + nt * 8 + lr * 2;
            float b0 = bias[col], b1 = bias[col + 1];
#pragma unroll
            for (int hh = 0; hh < 2; hh++) {
                int row = rbase + hh * 8;
                int orow = mapGraph ? (row / NN) * L_ + NQ + (row % NN) : row;
                float v0 = acc[mt][nt][hh * 2 + 0] + b0;
                float v1 = acc[mt][nt][hh * 2 + 1] + b1;
                if (EPI == 1) {
                    v0 += resid[(size_t)row * N + col];
                    v1 += resid[(size_t)row * N + col + 1];
                }
                if (EPI == 2) {
                    v0 = 0.5f * v0 * (1.0f + erff(v0 * 0.7071067811865475f));
                    v1 = 0.5f * v1 * (1.0f + erff(v1 * 0.7071067811865475f));
                }
                if (EPI == 2 || EPI == 3) {
                    ((uint32_t*)C)[(size_t)orow * (N >> 1) + (col >> 1)] =
                        pack_h2(v0, v1);
                } else {
                    *(float2*)(C + (size_t)orow * N + col) = make_float2(v0, v1);
                }
            }
        }
    }
}

// ============================================================================
// conversion passes
// ============================================================================
__global__ void cvt_h(const float* __restrict__ in, uint32_t* __restrict__ out,
                      int nwords)
{
    int w = (blockIdx.x * blockDim.x + threadIdx.x) * 2;
    if (w >= nwords) return;
    float4 v = *(const float4*)(in + 2 * w);
    *(uint2*)(out + w) = make_uint2(pack_h2(v.x, v.y), pack_h2(v.z, v.w));
}

__global__ void cvt_wh(const float* __restrict__ in, uint32_t* __restrict__ out,
                       int K, int N)
{
    const float* ip = in + (size_t)blockIdx.z * K * N;
    uint32_t* op = out + (size_t)blockIdx.z * (K / 2) * N;
    int idx = blockIdx.x * blockDim.x + threadIdx.x;
    int total = (K >> 1) * (N >> 2);
    if (idx >= total) return;
    int kp = idx / (N >> 2), ng = (idx % (N >> 2)) * 4;
    const float* r0 = ip + (size_t)(2 * kp) * N + ng;
    float4 a = *(const float4*)r0;
    float4 b = *(const float4*)(r0 + N);
    *(uint4*)(op + (size_t)kp * N + ng) =
        make_uint4(pack_h2(a.x, b.x), pack_h2(a.y, b.y),
                   pack_h2(a.z, b.z), pack_h2(a.w, b.w));
}

// ============================================================================
// Row LayerNorm (D=768); dual fp32 + fp16 output
// ============================================================================
__global__ __launch_bounds__(256)
void ln_kernel(const float* __restrict__ in, float* __restrict__ out,
               uint32_t* __restrict__ out_h,
               const float* __restrict__ g, const float* __restrict__ bta,
               const float* __restrict__ pos, const float* __restrict__ tok)
{
    const int row = blockIdx.x;
    const int l = row % L_;
    const int tid = threadIdx.x;
    const int lane = tid & 31, wid = tid >> 5;
    const float* ip = in + (size_t)row * D_;

    float v[3];
    float s = 0.f;
#pragma unroll
    for (int i = 0; i < 3; i++) {
        int d = tid + i * 256;
        float x = ip[d];
        if (pos) x += pos[l * D_ + d] + tok[d];
        v[i] = x;
        s += x;
    }
#pragma unroll
    for (int o = 16; o > 0; o >>= 1) s += __shfl_xor_sync(0xffffffffu, s, o);

    __shared__ float red[8];
    __shared__ float smean, sinv;
    if (lane == 0) red[wid] = s;
    __syncthreads();
    if (tid == 0) {
        float t = 0.f;
#pragma unroll
        for (int j = 0; j < 8; j++) t += red[j];
        smean = t * (1.0f / 768.0f);
    }
    __syncthreads();
    float mean = smean;

    float ss = 0.f;
#pragma unroll
    for (int i = 0; i < 3; i++) {
        float d0 = v[i] - mean;
        ss += d0 * d0;
    }
#pragma unroll
    for (int o = 16; o > 0; o >>= 1) ss += __shfl_xor_sync(0xffffffffu, ss, o);
    if (lane == 0) red[wid] = ss;
    __syncthreads();
    if (tid == 0) {
        float t = 0.f;
#pragma unroll
        for (int j = 0; j < 8; j++) t += red[j];
        sinv = rsqrtf(t * (1.0f / 768.0f) + 1e-12f);
    }
    __syncthreads();
    float inv = sinv;

    float* op = out + (size_t)row * D_;
    __half* oh = (__half*)(out_h + (size_t)row * (D_ / 2));
#pragma unroll
    for (int i = 0; i < 3; i++) {
        int d = tid + i * 256;
        float y = (v[i] - mean) * inv * g[d] + bta[d];
        op[d] = y;
        oh[d] = __float2half_rn(y);
    }
}

// ============================================================================
// FP16 attention. qkv words packed along channel. Q/K tiles [64][72] words,
// V repacked key-pair-wise [32][104] words, S [64][520] fp32 -> P packed.
// ============================================================================
constexpr int QW3 = 72;    // Q/K word stride (72%32==8 -> conflict-free)
constexpr int VW3 = 104;   // V word stride
constexpr int SW3 = 520;   // S stride
constexpr int ATTN_SMEM =
    (64 * QW3 + 2 * 64 * QW3 + 2 * 32 * VW3 + 64 * SW3 + 512) * 4;  // 217088 B

__global__ __launch_bounds__(256)
void attn_h(const uint32_t* __restrict__ qkv, uint32_t* __restrict__ ctxh,
            const int* __restrict__ text_atts, const int* __restrict__ graph_mask)
{
    const int bh = blockIdx.x;
    const int b = bh / H_, h = bh % H_;
    const int qt = blockIdx.y;
    const int tid = threadIdx.x;
    const int lane = tid & 31, wid = tid >> 5;
    const int lq = lane >> 2, lr = lane & 3;

    extern __shared__ uint32_t smu[];
    uint32_t* Qs = smu;                        // [64][QW3]
    uint32_t* Kb = Qs + 64 * QW3;              // 2 x [64][QW3]
    uint32_t* Vb = Kb + 2 * 64 * QW3;          // 2 x [32][VW3]
    uint32_t* Sb = Vb + 2 * 32 * VW3;          // [64][SW3]
    int* keep = (int*)(Sb + 64 * SW3);

    for (int j = tid; j < L_; j += 256)
        keep[j] = (j < NQ) ? 1
                : (j < TS) ? graph_mask[b * NN + (j - NQ)]
                           : text_atts[b * T_ + (j - TS)];

    // Q tile: 4 threads/row, 12 words each
    {
        const uint32_t* qbase = qkv + (size_t)(b * L_ + qt * 64) * QKVW_ + h * 48;
        int r = tid >> 2, w0 = (tid & 3) * 12;
#pragma unroll
        for (int i = 0; i < 3; i++)
            *(uint4*)&Qs[r * QW3 + w0 + 4 * i] =
                *(const uint4*)(qbase + (size_t)r * QKVW_ + w0 + 4 * i);
    }

    const int wm  = (wid >> 1) * 16;
    const int wnS = (wid & 1) * 32;
    const int wnV = (wid & 1) * 48;
    const float scale = 0.10206207261596577f;   // 1/sqrt(96)

    // ---- K loaders: 4 threads/row x 12 words ----
    uint4 preK[3];
    const int kr = tid >> 2, kw0 = (tid & 3) * 12;
    auto ldK = [&](int kc) {
        const uint32_t* base =
            qkv + (size_t)(b * L_ + kc * 64) * QKVW_ + 384 + h * 48;
#pragma unroll
        for (int i = 0; i < 3; i++)
            preK[i] = *(const uint4*)(base + (size_t)kr * QKVW_ + kw0 + 4 * i);
    };
    auto stK = [&](int buf) {
        uint32_t* K = Kb + buf * 64 * QW3;
#pragma unroll
        for (int i = 0; i < 3; i++)
            *(uint4*)&K[kr * QW3 + kw0 + 4 * i] = preK[i];
    };

    // ---- V loaders: key-pair repack. 8 threads/kp-row, 6 in-words each ----
    uint2 preVa[3], preVb[3];
    const int vkp = tid >> 3, vcw = (tid & 7) * 6;
    auto ldV = [&](int kc) {
        const uint32_t* base =
            qkv + (size_t)(b * L_ + kc * 64) * QKVW_ + 768 + h * 48;
        const uint32_t* rA = base + (size_t)(2 * vkp) * QKVW_ + vcw;
        const uint32_t* rB = rA + QKVW_;
#pragma unroll
        for (int i = 0; i < 3; i++) {
            preVa[i] = *(const uint2*)(rA + 2 * i);
            preVb[i] = *(const uint2*)(rB + 2 * i);
        }
    };
    auto stV = [&](int buf) {
        uint32_t* V = Vb + buf * 32 * VW3;
        uint32_t o[12];
#pragma unroll
        for (int i = 0; i < 3; i++) {
            o[4 * i + 0] = __byte_perm(preVa[i].x, preVb[i].x, 0x5410);
            o[4 * i + 1] = __byte_perm(preVa[i].x, preVb[i].x, 0x7632);
            o[4 * i + 2] = __byte_perm(preVa[i].y, preVb[i].y, 0x5410);
            o[4 * i + 3] = __byte_perm(preVa[i].y, preVb[i].y, 0x7632);
        }
        uint32_t* dst = &V[vkp * VW3 + 2 * vcw];
#pragma unroll
        for (int i = 0; i < 3; i++)
            *(uint4*)(dst + 4 * i) = *(uint4*)(o + 4 * i);
    };

    // ---------------- score phase ----------------
    ldK(0);
    stK(0);
    __syncthreads();
    for (int kc = 0; kc < 8; kc++) {
        if (kc < 7) ldK(kc + 1);

        const uint32_t* Ks = Kb + (kc & 1) * 64 * QW3;
        float sacc[4][4];
#pragma unroll
        for (int nt = 0; nt < 4; nt++)
#pragma unroll
            for (int r = 0; r < 4; r++) sacc[nt][r] = 0.f;

#pragma unroll
        for (int k8 = 0; k8 < 48; k8 += 8) {      // 6 k16 steps
            uint32_t af[4];
            const uint32_t* qp = &Qs[(wm + lq) * QW3 + k8 + lr];
            af[0] = qp[0];
            af[1] = qp[8 * QW3];
            af[2] = qp[4];
            af[3] = qp[8 * QW3 + 4];
#pragma unroll
            for (int nt = 0; nt < 4; nt++) {
                const uint32_t* kp2 = &Ks[(wnS + nt * 8 + lq) * QW3 + k8 + lr];
                uint32_t bf[2] = {kp2[0], kp2[4]};
                mma_f16(sacc[nt], af, bf);
            }
        }

        if (kc < 7) stK((kc + 1) & 1);

        float* Sf = (float*)Sb;
#pragma unroll
        for (int nt = 0; nt < 4; nt++) {
            int kg = kc * 64 + wnS + nt * 8 + 2 * lr;
            bool k0 = keep[kg] != 0, k1 = keep[kg + 1] != 0;
#pragma unroll
            for (int half = 0; half < 2; half++) {
                int qrow = wm + lq + half * 8;
                int qg = qt * 64 + qrow;
                bool qok = keep[qg] != 0;
                bool ok0 = qok && k0, ok1 = qok && k1;
                if (qg < TS) {                       // prefix cannot see text
                    if (kg     >= TS) ok0 = false;
                    if (kg + 1 >= TS) ok1 = false;
                } else {                             // text query: causal in text
                    if (kg     >= TS && qg < kg)     ok0 = false;
                    if (kg + 1 >= TS && qg < kg + 1) ok1 = false;
                }
                float v0 = sacc[nt][half * 2 + 0] * scale + (ok0 ? 0.f : NEGB);
                float v1 = sacc[nt][half * 2 + 1] * scale + (ok1 ? 0.f : NEGB);
                *(float2*)&Sf[qrow * SW3 + kg] = make_float2(v0, v1);
            }
        }
        __syncthreads();
    }

    // ---- softmax (4 threads/row) + pack P as half2 key-pairs in-place ----
    ldV(0);
    {
        int r = tid >> 2, p = tid & 3;
        float* row = (float*)Sb + r * SW3 + p * 128;
        float m = -INFINITY;
#pragma unroll 4
        for (int k = 0; k < 128; k++) m = fmaxf(m, row[k]);
        m = fmaxf(m, __shfl_xor_sync(0xffffffffu, m, 1));
        m = fmaxf(m, __shfl_xor_sync(0xffffffffu, m, 2));
        float sum = 0.f;
#pragma unroll 4
        for (int k = 0; k < 128; k++) {
            float e = __expf(row[k] - m);
            row[k] = e;
            sum += e;
        }
        sum += __shfl_xor_sync(0xffffffffu, sum, 1);
        sum += __shfl_xor_sync(0xffffffffu, sum, 2);
        float inv = 1.f / sum;
        // pack into own float region: word j <- keys 2j, 2j+1 (j = 0..63)
        uint32_t* rowp = Sb + r * SW3 + p * 128;
#pragma unroll 4
        for (int j = 0; j < 64; j++) {
            float e0 = row[2 * j] * inv;
            float e1 = row[2 * j + 1] * inv;
            rowp[j] = pack_h2(e0, e1);
        }
    }
    stV(0);
    __syncthreads();

    // ---------------- P @ V phase ----------------
    float oacc[6][4];
#pragma unroll
    for (int nt = 0; nt < 6; nt++)
#pragma unroll
        for (int r = 0; r < 4; r++) oacc[nt][r] = 0.f;

    for (int kc = 0; kc < 8; kc++) {
        if (kc < 7) ldV(kc + 1);

        const uint32_t* Vs = Vb + (kc & 1) * 32 * VW3;
        // P word index for kp = kc*32 + w: stored at p*128 + (kp - p*64),
        // p = kc>>1  =>  base = kc*32 + (kc>>1)*64
        const int pbase = (wm + lq) * SW3 + kc * 32 + (kc >> 1) * 64;
#pragma unroll
        for (int k8 = 0; k8 < 32; k8 += 8) {      // 4 k16 steps (64 keys)
            uint32_t af[4];
            const uint32_t* pp = &Sb[pbase + k8 + lr];
            af[0] = pp[0];
            af[1] = pp[8 * SW3];
            af[2] = pp[4];
            af[3] = pp[8 * SW3 + 4];
#pragma unroll
            for (int nt = 0; nt < 6; nt++) {
                const uint32_t* vp = &Vs[(k8 + lr) * VW3 + wnV + nt * 8 + lq];
                uint32_t bf[2] = {vp[0], vp[4 * VW3]};
                mma_f16(oacc[nt], af, bf);
            }
        }

        if (kc < 7) {
            stV((kc + 1) & 1);
            __syncthreads();
        }
    }

    // ctx -> half2 packed along channel
#pragma unroll
    for (int nt = 0; nt < 6; nt++) {
#pragma unroll
        for (int half = 0; half < 2; half++) {
            int qrow = qt * 64 + wm + lq + half * 8;
            int col = h * HD + wnV + nt * 8 + 2 * lr;   // even
            ctxh[(size_t)(b * L_ + qrow) * (D_ / 2) + (col >> 1)] =
                pack_h2(oacc[nt][half * 2 + 0], oacc[nt][half * 2 + 1]);
        }
    }
}

// ============================================================================
// misc elementwise
// ============================================================================
__global__ void fill_embed(const float* __restrict__ qtok,
                           const float* __restrict__ temb,
                           float* __restrict__ out)
{
    int idx = blockIdx.x * blockDim.x + threadIdx.x;
    if (idx >= B_ * L_ * D_) return;
    int rem = idx % (L_ * D_);
    int b = idx / (L_ * D_);
    int l = rem / D_, d = rem % D_;
    if (l < NQ)
        out[idx] = qtok[l * D_ + d];
    else if (l >= TS)
        out[idx] = temb[(size_t)(b * T_ + (l - TS)) * D_ + d];
}

__global__ void copy_out(const float* __restrict__ x, float* __restrict__ out, int n)
{
    int idx = blockIdx.x * blockDim.x + threadIdx.x;
    if (idx >= n) return;
    int rem = idx % (T_ * D_);
    int b = idx / (T_ * D_);
    int t = rem / D_, d = rem % D_;
    out[idx] = x[(size_t)(b * L_ + TS + t) * D_ + d];
}

// ============================================================================
// launcher
// ============================================================================
extern "C" void kernel_launch(void* const* d_in, const int* in_sizes, int n_in,
                              void* d_out, int out_size)
{
    const float* gnf     = (const float*)d_in[0];
    const float* temb    = (const float*)d_in[1];
    const int*   tatt    = (const int*)  d_in[2];
    const int*   gmask   = (const int*)  d_in[3];
    const float* qtok    = (const float*)d_in[4];
    const float* gproj_w = (const float*)d_in[5];
    const float* gproj_b = (const float*)d_in[6];
    const float* pos     = (const float*)d_in[7];
    const float* tok     = (const float*)d_in[8];
    const float* elng    = (const float*)d_in[9];
    const float* elnb    = (const float*)d_in[10];
    const float* qkvw    = (const float*)d_in[11];
    const float* qkvb    = (const float*)d_in[12];
    const float* aow     = (const float*)d_in[13];
    const float* aob     = (const float*)d_in[14];
    const float* ln1g    = (const float*)d_in[15];
    const float* ln1b    = (const float*)d_in[16];
    const float* ff1w    = (const float*)d_in[17];
    const float* ff1b    = (const float*)d_in[18];
    const float* ff2w    = (const float*)d_in[19];
    const float* ff2b    = (const float*)d_in[20];
    const float* ln2g    = (const float*)d_in[21];
    const float* ln2b    = (const float*)d_in[22];

    float *px, *ptmp;
    uint32_t *pqkvh, *pxh, *pctxh, *pffh;
    uint32_t *pqkvwh, *paowh, *pff1wh, *pff2wh, *pgpwh, *pgnfh;
    cudaGetSymbolAddress((void**)&px,    g_x);
    cudaGetSymbolAddress((void**)&ptmp,  g_tmp);
    cudaGetSymbolAddress((void**)&pqkvh, g_qkvh);
    cudaGetSymbolAddress((void**)&pxh,   g_xh);
    cudaGetSymbolAddress((void**)&pctxh, g_ctxh);
    cudaGetSymbolAddress((void**)&pffh,  g_ffh);
    cudaGetSymbolAddress((void**)&pqkvwh, g_qkvw_h);
    cudaGetSymbolAddress((void**)&paowh,  g_aow_h);
    cudaGetSymbolAddress((void**)&pff1wh, g_ff1w_h);
    cudaGetSymbolAddress((void**)&pff2wh, g_ff2w_h);
    cudaGetSymbolAddress((void**)&pgpwh,  g_gpw_h);
    cudaGetSymbolAddress((void**)&pgnfh,  g_gnf_h);

    cudaFuncSetAttribute(attn_h, cudaFuncAttributeMaxDynamicSharedMemorySize,
                         ATTN_SMEM);

    const int NROWS = B_ * L_;   // 8192

    // ---- one-time weight packing: fp32 [K,N] -> half2 [K/2][N] ----
    auto wh = [](const float* in, uint32_t* out, int K, int N, int layers) {
        int total = (K / 2) * (N / 4);
        dim3 gr((total + 255) / 256, 1, layers);
        cvt_wh<<<gr, 256>>>(in, out, K, N);
    };
    wh(qkvw,    pqkvwh, D_, 3 * D_, NLAY);
    wh(aow,     paowh,  D_, D_,     NLAY);
    wh(ff1w,    pff1wh, D_, FF,     NLAY);
    wh(ff2w,    pff2wh, FF, D_,     NLAY);
    wh(gproj_w, pgpwh,  D_, D_,     1);
    cvt_h<<<(B_ * NN * D_ / 2 / 2 + 255) / 256, 256>>>(gnf, pgnfh, B_ * NN * D_ / 2);

    // ---- embeddings ----
    fill_embed<<<(B_ * L_ * D_ + 255) / 256, 256>>>(qtok, temb, ptmp);
    hgemm<0><<<dim3(D_ / 128, (B_ * NN) / 128), 256>>>(
        pgnfh, pgpwh, gproj_b, nullptr, ptmp, B_ * NN, D_, D_, 1);
    ln_kernel<<<NROWS, 256>>>(ptmp, px, pxh, elng, elnb, pos, tok);

    // ---- 6 encoder layers ----
    for (int i = 0; i < NLAY; i++) {
        // qkv projection — fp16 GEMM, half2-packed output for fp16 attention
        hgemm<3><<<dim3((3 * D_) / 128, NROWS / 128), 256>>>(
            pxh, pqkvwh + (size_t)i * (D_ / 2) * 3 * D_,
            qkvb + (size_t)i * 3 * D_, nullptr, (float*)pqkvh,
            NROWS, 3 * D_, D_, 0);

        attn_h<<<dim3(B_ * H_, L_ / 64), 256, ATTN_SMEM>>>(
            pqkvh, pctxh, tatt, gmask);

        hgemm<1><<<dim3(D_ / 128, NROWS / 128), 256>>>(
            pctxh, paowh + (size_t)i * (D_ / 2) * D_,
            aob + (size_t)i * D_, px, ptmp, NROWS, D_, D_, 0);
        ln_kernel<<<NROWS, 256>>>(ptmp, px, pxh, ln1g + (size_t)i * D_,
                                  ln1b + (size_t)i * D_, nullptr, nullptr);

        hgemm<2><<<dim3(FF / 128, NROWS / 128), 256>>>(
            pxh, pff1wh + (size_t)i * (D_ / 2) * FF,
            ff1b + (size_t)i * FF, nullptr, (float*)pffh, NROWS, FF, D_, 0);

        hgemm<1><<<dim3(D_ / 128, NROWS / 128), 256>>>(
            pffh, pff2wh + (size_t)i * (FF / 2) * D_,
            ff2b + (size_t)i * D_, px, ptmp, NROWS, D_, FF, 0);
        ln_kernel<<<NROWS, 256>>>(ptmp, px, pxh, ln2g + (size_t)i * D_,
                                  ln2b + (size_t)i * D_, nullptr, nullptr);
    }

    // ---- output: text rows ----
    copy_out<<<(out_size + 255) / 256, 256>>>(px, (float*)d_out, out_size);
}

// round 15
// speedup vs baseline: 2.0054x; 1.1014x over previous
#include <cuda_runtime.h>
#include <cuda_fp16.h>
#include <math.h>
#include <stdint.h>

// ---------------- problem dims ----------------
constexpr int B_   = 16;
constexpr int NQ   = 32;
constexpr int NN   = 128;
constexpr int T_   = 352;
constexpr int D_   = 768;
constexpr int H_   = 8;
constexpr int NLAY = 6;
constexpr int FF   = 3072;
constexpr int L_   = NQ + NN + T_;   // 512
constexpr int TS   = NQ + NN;        // 160
constexpr int HD   = D_ / H_;        // 96
constexpr float NEGB = -1e9f;
constexpr int QKVW_ = 3 * D_ / 2;    // 1152 words per qkv row

// ---------------- device scratch ----------------
__device__ float    g_x  [B_ * L_ * D_];
__device__ float    g_tmp[B_ * L_ * D_];
__device__ uint32_t g_qkvh[B_ * L_ * QKVW_];

__device__ uint32_t g_xh  [B_ * L_ * D_ / 2];
__device__ uint32_t g_ctxh[B_ * L_ * D_ / 2];
__device__ uint32_t g_ffh [B_ * L_ * FF / 2];

__device__ uint32_t g_qkvw_h[NLAY * D_ / 2 * 3 * D_];
__device__ uint32_t g_aow_h [NLAY * D_ / 2 * D_];
__device__ uint32_t g_ff1w_h[NLAY * D_ / 2 * FF];
__device__ uint32_t g_ff2w_h[NLAY * FF / 2 * D_];
__device__ uint32_t g_gpw_h [D_ / 2 * D_];
__device__ uint32_t g_gnf_h [B_ * NN * D_ / 2];

// ---------------- helpers ----------------
__device__ __forceinline__ uint32_t pack_h2(float lo, float hi) {
    __half2 h = __floats2half2_rn(lo, hi);
    return *reinterpret_cast<uint32_t*>(&h);
}

__device__ __forceinline__ void mma_f16(float c[4], const uint32_t a[4],
                                        const uint32_t b[2]) {
    asm volatile(
        "mma.sync.aligned.m16n8k16.row.col.f32.f16.f16.f32 "
        "{%0,%1,%2,%3}, {%4,%5,%6,%7}, {%8,%9}, {%0,%1,%2,%3};"
        : "+f"(c[0]), "+f"(c[1]), "+f"(c[2]), "+f"(c[3])
        : "r"(a[0]), "r"(a[1]), "r"(a[2]), "r"(a[3]), "r"(b[0]), "r"(b[1]));
}

__device__ __forceinline__ void ldsm4(uint32_t r[4], uint32_t addr) {
    asm volatile(
        "ldmatrix.sync.aligned.m8n8.x4.shared.b16 {%0,%1,%2,%3}, [%4];"
        : "=r"(r[0]), "=r"(r[1]), "=r"(r[2]), "=r"(r[3]) : "r"(addr));
}

// ============================================================================
// FP16 GEMM. A: [M,K/2] words. B: [K/2,N] words. A-fragments via ldmatrix.x4.
// EPI: 0 = +bias fp32   1 = +bias+resid fp32   2 = gelu -> half2 packed
//      3 = +bias -> half2 packed (qkv)
// ============================================================================
constexpr int ASTR = 20;
constexpr int BSTR = 136;

template <int EPI>
__global__ __launch_bounds__(256)
void hgemm(const uint32_t* __restrict__ A, const uint32_t* __restrict__ Bm,
           const float* __restrict__ bias, const float* __restrict__ resid,
           float* __restrict__ C, int M, int N, int K, int mapGraph)
{
    __shared__ uint32_t As[2][128 * ASTR];
    __shared__ uint32_t Bs[2][16 * BSTR];

    const int tid  = threadIdx.x;
    const int br   = blockIdx.y, bc = blockIdx.x;
    const int lane = tid & 31,  wid = tid >> 5;
    const int wm = (wid >> 2) * 64;
    const int wn = (wid & 3) * 32;
    const int lq = lane >> 2;
    const int lr = lane & 3;
    // ldmatrix per-lane row/k decomposition
    const int mrow = ((lane >> 3) & 1) * 8 + (lane & 7);
    const int koff = (lane >> 4) * 4;

    float acc[4][4][4];
#pragma unroll
    for (int mt = 0; mt < 4; mt++)
#pragma unroll
        for (int nt = 0; nt < 4; nt++)
#pragma unroll
            for (int r = 0; r < 4; r++) acc[mt][nt][r] = 0.f;

    const int Kw  = K >> 1;
    const int nkt = K >> 5;
    uint4 pa[2], pb[2];

    auto ldA = [&](int kt) {
#pragma unroll
        for (int i = 0; i < 2; i++) {
            int id  = tid + i * 256;
            int row = id >> 2, cg = (id & 3) << 2;
            pa[i] = *(const uint4*)(A + (size_t)(br * 128 + row) * Kw + kt * 16 + cg);
        }
    };
    auto ldB = [&](int kt) {
#pragma unroll
        for (int i = 0; i < 2; i++) {
            int id  = tid + i * 256;
            int row = id >> 5, cg = (id & 31) << 2;
            pb[i] = *(const uint4*)(Bm + (size_t)(kt * 16 + row) * N + bc * 128 + cg);
        }
    };
    auto stAB = [&](int buf) {
#pragma unroll
        for (int i = 0; i < 2; i++) {
            int id  = tid + i * 256;
            int row = id >> 2, cg = (id & 3) << 2;
            *(uint4*)&As[buf][row * ASTR + cg] = pa[i];
        }
#pragma unroll
        for (int i = 0; i < 2; i++) {
            int id  = tid + i * 256;
            int row = id >> 5, cg = (id & 31) << 2;
            *(uint4*)&Bs[buf][row * BSTR + cg] = pb[i];
        }
    };
    auto compute = [&](int buf) {
        uint32_t abase = (uint32_t)__cvta_generic_to_shared(&As[buf][0]);
#pragma unroll
        for (int k8 = 0; k8 < 16; k8 += 8) {
            uint32_t af[4][4], bf[4][2];
#pragma unroll
            for (int mt = 0; mt < 4; mt++)
                ldsm4(af[mt],
                      abase + (uint32_t)((wm + mt * 16 + mrow) * ASTR + k8 + koff) * 4);
#pragma unroll
            for (int nt = 0; nt < 4; nt++) {
                const uint32_t* p = &Bs[buf][(k8 + lr) * BSTR + wn + nt * 8 + lq];
                bf[nt][0] = p[0];
                bf[nt][1] = p[4 * BSTR];
            }
#pragma unroll
            for (int mt = 0; mt < 4; mt++)
#pragma unroll
                for (int nt = 0; nt < 4; nt++)
                    mma_f16(acc[mt][nt], af[mt], bf[nt]);
        }
    };

    ldA(0); ldB(0);
    stAB(0);
    __syncthreads();
    for (int kt = 0; kt < nkt; kt++) {
        int buf = kt & 1;
        bool more = (kt + 1 < nkt);
        if (more) { ldA(kt + 1); ldB(kt + 1); }
        compute(buf);
        if (more) stAB(buf ^ 1);
        __syncthreads();
    }

    // ---- epilogue ----
#pragma unroll
    for (int mt = 0; mt < 4; mt++) {
        int rbase = br * 128 + wm + mt * 16 + lq;
#pragma unroll
        for (int nt = 0; nt < 4; nt++) {
            int col = bc * 128 + wn + nt * 8 + lr * 2;
            float b0 = bias[col], b1 = bias[col + 1];
#pragma unroll
            for (int hh = 0; hh < 2; hh++) {
                int row = rbase + hh * 8;
                int orow = mapGraph ? (row / NN) * L_ + NQ + (row % NN) : row;
                float v0 = acc[mt][nt][hh * 2 + 0] + b0;
                float v1 = acc[mt][nt][hh * 2 + 1] + b1;
                if (EPI == 1) {
                    v0 += resid[(size_t)row * N + col];
                    v1 += resid[(size_t)row * N + col + 1];
                }
                if (EPI == 2) {
                    v0 = 0.5f * v0 * (1.0f + erff(v0 * 0.7071067811865475f));
                    v1 = 0.5f * v1 * (1.0f + erff(v1 * 0.7071067811865475f));
                }
                if (EPI == 2 || EPI == 3) {
                    ((uint32_t*)C)[(size_t)orow * (N >> 1) + (col >> 1)] =
                        pack_h2(v0, v1);
                } else {
                    *(float2*)(C + (size_t)orow * N + col) = make_float2(v0, v1);
                }
            }
        }
    }
}

// ============================================================================
// conversion passes
// ============================================================================
__global__ void cvt_h(const float* __restrict__ in, uint32_t* __restrict__ out,
                      int nwords)
{
    int w = (blockIdx.x * blockDim.x + threadIdx.x) * 2;
    if (w >= nwords) return;
    float4 v = *(const float4*)(in + 2 * w);
    *(uint2*)(out + w) = make_uint2(pack_h2(v.x, v.y), pack_h2(v.z, v.w));
}

__global__ void cvt_wh(const float* __restrict__ in, uint32_t* __restrict__ out,
                       int K, int N)
{
    const float* ip = in + (size_t)blockIdx.z * K * N;
    uint32_t* op = out + (size_t)blockIdx.z * (K / 2) * N;
    int idx = blockIdx.x * blockDim.x + threadIdx.x;
    int total = (K >> 1) * (N >> 2);
    if (idx >= total) return;
    int kp = idx / (N >> 2), ng = (idx % (N >> 2)) * 4;
    const float* r0 = ip + (size_t)(2 * kp) * N + ng;
    float4 a = *(const float4*)r0;
    float4 b = *(const float4*)(r0 + N);
    *(uint4*)(op + (size_t)kp * N + ng) =
        make_uint4(pack_h2(a.x, b.x), pack_h2(a.y, b.y),
                   pack_h2(a.z, b.z), pack_h2(a.w, b.w));
}

// ============================================================================
// Row LayerNorm (D=768); dual fp32 + fp16 output
// ============================================================================
__global__ __launch_bounds__(256)
void ln_kernel(const float* __restrict__ in, float* __restrict__ out,
               uint32_t* __restrict__ out_h,
               const float* __restrict__ g, const float* __restrict__ bta,
               const float* __restrict__ pos, const float* __restrict__ tok)
{
    const int row = blockIdx.x;
    const int l = row % L_;
    const int tid = threadIdx.x;
    const int lane = tid & 31, wid = tid >> 5;
    const float* ip = in + (size_t)row * D_;

    float v[3];
    float s = 0.f;
#pragma unroll
    for (int i = 0; i < 3; i++) {
        int d = tid + i * 256;
        float x = ip[d];
        if (pos) x += pos[l * D_ + d] + tok[d];
        v[i] = x;
        s += x;
    }
#pragma unroll
    for (int o = 16; o > 0; o >>= 1) s += __shfl_xor_sync(0xffffffffu, s, o);

    __shared__ float red[8];
    __shared__ float smean, sinv;
    if (lane == 0) red[wid] = s;
    __syncthreads();
    if (tid == 0) {
        float t = 0.f;
#pragma unroll
        for (int j = 0; j < 8; j++) t += red[j];
        smean = t * (1.0f / 768.0f);
    }
    __syncthreads();
    float mean = smean;

    float ss = 0.f;
#pragma unroll
    for (int i = 0; i < 3; i++) {
        float d0 = v[i] - mean;
        ss += d0 * d0;
    }
#pragma unroll
    for (int o = 16; o > 0; o >>= 1) ss += __shfl_xor_sync(0xffffffffu, ss, o);
    if (lane == 0) red[wid] = ss;
    __syncthreads();
    if (tid == 0) {
        float t = 0.f;
#pragma unroll
        for (int j = 0; j < 8; j++) t += red[j];
        sinv = rsqrtf(t * (1.0f / 768.0f) + 1e-12f);
    }
    __syncthreads();
    float inv = sinv;

    float* op = out + (size_t)row * D_;
    __half* oh = (__half*)(out_h + (size_t)row * (D_ / 2));
#pragma unroll
    for (int i = 0; i < 3; i++) {
        int d = tid + i * 256;
        float y = (v[i] - mean) * inv * g[d] + bta[d];
        op[d] = y;
        oh[d] = __float2half_rn(y);
    }
}

// ============================================================================
// FP16 attention with causal chunk skipping.
// Chunk c is fully masked for query tile qt when c >= 3 and c > qt
// (text keys beyond every query; prefix queries never see text).
// nch(qt) = max(3, qt+1). Skipped chunks contributed exact zeros before.
// ============================================================================
constexpr int QW3 = 72;
constexpr int VW3 = 104;
constexpr int SW3 = 520;
constexpr int ATTN_SMEM =
    (64 * QW3 + 2 * 64 * QW3 + 2 * 32 * VW3 + 64 * SW3 + 512) * 4;

__global__ __launch_bounds__(256)
void attn_h(const uint32_t* __restrict__ qkv, uint32_t* __restrict__ ctxh,
            const int* __restrict__ text_atts, const int* __restrict__ graph_mask)
{
    const int bh = blockIdx.x;
    const int b = bh / H_, h = bh % H_;
    const int qt = blockIdx.y;
    const int tid = threadIdx.x;
    const int lane = tid & 31, wid = tid >> 5;
    const int lq = lane >> 2, lr = lane & 3;

    const int nch = (qt < 3) ? 3 : (qt + 1);   // live key chunks for this tile

    extern __shared__ uint32_t smu[];
    uint32_t* Qs = smu;
    uint32_t* Kb = Qs + 64 * QW3;
    uint32_t* Vb = Kb + 2 * 64 * QW3;
    uint32_t* Sb = Vb + 2 * 32 * VW3;
    int* keep = (int*)(Sb + 64 * SW3);

    for (int j = tid; j < L_; j += 256)
        keep[j] = (j < NQ) ? 1
                : (j < TS) ? graph_mask[b * NN + (j - NQ)]
                           : text_atts[b * T_ + (j - TS)];

    {
        const uint32_t* qbase = qkv + (size_t)(b * L_ + qt * 64) * QKVW_ + h * 48;
        int r = tid >> 2, w0 = (tid & 3) * 12;
#pragma unroll
        for (int i = 0; i < 3; i++)
            *(uint4*)&Qs[r * QW3 + w0 + 4 * i] =
                *(const uint4*)(qbase + (size_t)r * QKVW_ + w0 + 4 * i);
    }

    const int wm  = (wid >> 1) * 16;
    const int wnS = (wid & 1) * 32;
    const int wnV = (wid & 1) * 48;
    const float scale = 0.10206207261596577f;

    uint4 preK[3];
    const int kr = tid >> 2, kw0 = (tid & 3) * 12;
    auto ldK = [&](int kc) {
        const uint32_t* base =
            qkv + (size_t)(b * L_ + kc * 64) * QKVW_ + 384 + h * 48;
#pragma unroll
        for (int i = 0; i < 3; i++)
            preK[i] = *(const uint4*)(base + (size_t)kr * QKVW_ + kw0 + 4 * i);
    };
    auto stK = [&](int buf) {
        uint32_t* K = Kb + buf * 64 * QW3;
#pragma unroll
        for (int i = 0; i < 3; i++)
            *(uint4*)&K[kr * QW3 + kw0 + 4 * i] = preK[i];
    };

    uint2 preVa[3], preVb[3];
    const int vkp = tid >> 3, vcw = (tid & 7) * 6;
    auto ldV = [&](int kc) {
        const uint32_t* base =
            qkv + (size_t)(b * L_ + kc * 64) * QKVW_ + 768 + h * 48;
        const uint32_t* rA = base + (size_t)(2 * vkp) * QKVW_ + vcw;
        const uint32_t* rB = rA + QKVW_;
#pragma unroll
        for (int i = 0; i < 3; i++) {
            preVa[i] = *(const uint2*)(rA + 2 * i);
            preVb[i] = *(const uint2*)(rB + 2 * i);
        }
    };
    auto stV = [&](int buf) {
        uint32_t* V = Vb + buf * 32 * VW3;
        uint32_t o[12];
#pragma unroll
        for (int i = 0; i < 3; i++) {
            o[4 * i + 0] = __byte_perm(preVa[i].x, preVb[i].x, 0x5410);
            o[4 * i + 1] = __byte_perm(preVa[i].x, preVb[i].x, 0x7632);
            o[4 * i + 2] = __byte_perm(preVa[i].y, preVb[i].y, 0x5410);
            o[4 * i + 3] = __byte_perm(preVa[i].y, preVb[i].y, 0x7632);
        }
        uint32_t* dst = &V[vkp * VW3 + 2 * vcw];
#pragma unroll
        for (int i = 0; i < 3; i++)
            *(uint4*)(dst + 4 * i) = *(uint4*)(o + 4 * i);
    };

    // ---------------- score phase (only live chunks) ----------------
    ldK(0);
    stK(0);
    __syncthreads();
    for (int kc = 0; kc < nch; kc++) {
        if (kc + 1 < nch) ldK(kc + 1);

        const uint32_t* Ks = Kb + (kc & 1) * 64 * QW3;
        float sacc[4][4];
#pragma unroll
        for (int nt = 0; nt < 4; nt++)
#pragma unroll
            for (int r = 0; r < 4; r++) sacc[nt][r] = 0.f;

#pragma unroll
        for (int k8 = 0; k8 < 48; k8 += 8) {
            uint32_t af[4];
            const uint32_t* qp = &Qs[(wm + lq) * QW3 + k8 + lr];
            af[0] = qp[0];
            af[1] = qp[8 * QW3];
            af[2] = qp[4];
            af[3] = qp[8 * QW3 + 4];
#pragma unroll
            for (int nt = 0; nt < 4; nt++) {
                const uint32_t* kp2 = &Ks[(wnS + nt * 8 + lq) * QW3 + k8 + lr];
                uint32_t bf[2] = {kp2[0], kp2[4]};
                mma_f16(sacc[nt], af, bf);
            }
        }

        if (kc + 1 < nch) stK((kc + 1) & 1);

        float* Sf = (float*)Sb;
#pragma unroll
        for (int nt = 0; nt < 4; nt++) {
            int kg = kc * 64 + wnS + nt * 8 + 2 * lr;
            bool k0 = keep[kg] != 0, k1 = keep[kg + 1] != 0;
#pragma unroll
            for (int half = 0; half < 2; half++) {
                int qrow = wm + lq + half * 8;
                int qg = qt * 64 + qrow;
                bool qok = keep[qg] != 0;
                bool ok0 = qok && k0, ok1 = qok && k1;
                if (qg < TS) {
                    if (kg     >= TS) ok0 = false;
                    if (kg + 1 >= TS) ok1 = false;
                } else {
                    if (kg     >= TS && qg < kg)     ok0 = false;
                    if (kg + 1 >= TS && qg < kg + 1) ok1 = false;
                }
                float v0 = sacc[nt][half * 2 + 0] * scale + (ok0 ? 0.f : NEGB);
                float v1 = sacc[nt][half * 2 + 1] * scale + (ok1 ? 0.f : NEGB);
                *(float2*)&Sf[qrow * SW3 + kg] = make_float2(v0, v1);
            }
        }
        __syncthreads();
    }

    // ---- softmax over live region only; pack P as half2 key-pairs ----
    ldV(0);
    {
        const int limit = nch * 64;          // live keys
        int r = tid >> 2, p = tid & 3;
        int base = p * 128;
        int cnt = limit - base;
        cnt = cnt < 0 ? 0 : (cnt > 128 ? 128 : cnt);
        float* row = (float*)Sb + r * SW3 + base;
        float m = -INFINITY;
#pragma unroll 4
        for (int k = 0; k < cnt; k++) m = fmaxf(m, row[k]);
        m = fmaxf(m, __shfl_xor_sync(0xffffffffu, m, 1));
        m = fmaxf(m, __shfl_xor_sync(0xffffffffu, m, 2));
        float sum = 0.f;
#pragma unroll 4
        for (int k = 0; k < cnt; k++) {
            float e = __expf(row[k] - m);
            row[k] = e;
            sum += e;
        }
        sum += __shfl_xor_sync(0xffffffffu, sum, 1);
        sum += __shfl_xor_sync(0xffffffffu, sum, 2);
        float inv = 1.f / sum;
        uint32_t* rowp = Sb + r * SW3 + base;
        int cntw = cnt >> 1;
#pragma unroll 4
        for (int j = 0; j < cntw; j++) {
            float e0 = row[2 * j] * inv;
            float e1 = row[2 * j + 1] * inv;
            rowp[j] = pack_h2(e0, e1);
        }
    }
    stV(0);
    __syncthreads();

    // ---------------- P @ V phase (only live chunks) ----------------
    float oacc[6][4];
#pragma unroll
    for (int nt = 0; nt < 6; nt++)
#pragma unroll
        for (int r = 0; r < 4; r++) oacc[nt][r] = 0.f;

    for (int kc = 0; kc < nch; kc++) {
        if (kc + 1 < nch) ldV(kc + 1);

        const uint32_t* Vs = Vb + (kc & 1) * 32 * VW3;
        const int pbase = (wm + lq) * SW3 + kc * 32 + (kc >> 1) * 64;
#pragma unroll
        for (int k8 = 0; k8 < 32; k8 += 8) {
            uint32_t af[4];
            const uint32_t* pp = &Sb[pbase + k8 + lr];
            af[0] = pp[0];
            af[1] = pp[8 * SW3];
            af[2] = pp[4];
            af[3] = pp[8 * SW3 + 4];
#pragma unroll
            for (int nt = 0; nt < 6; nt++) {
                const uint32_t* vp = &Vs[(k8 + lr) * VW3 + wnV + nt * 8 + lq];
                uint32_t bf[2] = {vp[0], vp[4 * VW3]};
                mma_f16(oacc[nt], af, bf);
            }
        }

        if (kc + 1 < nch) {
            stV((kc + 1) & 1);
            __syncthreads();
        }
    }

#pragma unroll
    for (int nt = 0; nt < 6; nt++) {
#pragma unroll
        for (int half = 0; half < 2; half++) {
            int qrow = qt * 64 + wm + lq + half * 8;
            int col = h * HD + wnV + nt * 8 + 2 * lr;
            ctxh[(size_t)(b * L_ + qrow) * (D_ / 2) + (col >> 1)] =
                pack_h2(oacc[nt][half * 2 + 0], oacc[nt][half * 2 + 1]);
        }
    }
}

// ============================================================================
// misc elementwise
// ============================================================================
__global__ void fill_embed(const float* __restrict__ qtok,
                           const float* __restrict__ temb,
                           float* __restrict__ out)
{
    int idx = blockIdx.x * blockDim.x + threadIdx.x;
    if (idx >= B_ * L_ * D_) return;
    int rem = idx % (L_ * D_);
    int b = idx / (L_ * D_);
    int l = rem / D_, d = rem % D_;
    if (l < NQ)
        out[idx] = qtok[l * D_ + d];
    else if (l >= TS)
        out[idx] = temb[(size_t)(b * T_ + (l - TS)) * D_ + d];
}

__global__ void copy_out(const float* __restrict__ x, float* __restrict__ out, int n)
{
    int idx = blockIdx.x * blockDim.x + threadIdx.x;
    if (idx >= n) return;
    int rem = idx % (T_ * D_);
    int b = idx / (T_ * D_);
    int t = rem / D_, d = rem % D_;
    out[idx] = x[(size_t)(b * L_ + TS + t) * D_ + d];
}

// ============================================================================
// launcher
// ============================================================================
extern "C" void kernel_launch(void* const* d_in, const int* in_sizes, int n_in,
                              void* d_out, int out_size)
{
    const float* gnf     = (const float*)d_in[0];
    const float* temb    = (const float*)d_in[1];
    const int*   tatt    = (const int*)  d_in[2];
    const int*   gmask   = (const int*)  d_in[3];
    const float* qtok    = (const float*)d_in[4];
    const float* gproj_w = (const float*)d_in[5];
    const float* gproj_b = (const float*)d_in[6];
    const float* pos     = (const float*)d_in[7];
    const float* tok     = (const float*)d_in[8];
    const float* elng    = (const float*)d_in[9];
    const float* elnb    = (const float*)d_in[10];
    const float* qkvw    = (const float*)d_in[11];
    const float* qkvb    = (const float*)d_in[12];
    const float* aow     = (const float*)d_in[13];
    const float* aob     = (const float*)d_in[14];
    const float* ln1g    = (const float*)d_in[15];
    const float* ln1b    = (const float*)d_in[16];
    const float* ff1w    = (const float*)d_in[17];
    const float* ff1b    = (const float*)d_in[18];
    const float* ff2w    = (const float*)d_in[19];
    const float* ff2b    = (const float*)d_in[20];
    const float* ln2g    = (const float*)d_in[21];
    const float* ln2b    = (const float*)d_in[22];

    float *px, *ptmp;
    uint32_t *pqkvh, *pxh, *pctxh, *pffh;
    uint32_t *pqkvwh, *paowh, *pff1wh, *pff2wh, *pgpwh, *pgnfh;
    cudaGetSymbolAddress((void**)&px,    g_x);
    cudaGetSymbolAddress((void**)&ptmp,  g_tmp);
    cudaGetSymbolAddress((void**)&pqkvh, g_qkvh);
    cudaGetSymbolAddress((void**)&pxh,   g_xh);
    cudaGetSymbolAddress((void**)&pctxh, g_ctxh);
    cudaGetSymbolAddress((void**)&pffh,  g_ffh);
    cudaGetSymbolAddress((void**)&pqkvwh, g_qkvw_h);
    cudaGetSymbolAddress((void**)&paowh,  g_aow_h);
    cudaGetSymbolAddress((void**)&pff1wh, g_ff1w_h);
    cudaGetSymbolAddress((void**)&pff2wh, g_ff2w_h);
    cudaGetSymbolAddress((void**)&pgpwh,  g_gpw_h);
    cudaGetSymbolAddress((void**)&pgnfh,  g_gnf_h);

    cudaFuncSetAttribute(attn_h, cudaFuncAttributeMaxDynamicSharedMemorySize,
                         ATTN_SMEM);

    const int NROWS = B_ * L_;   // 8192

    // ---- one-time weight packing ----
    auto wh = [](const float* in, uint32_t* out, int K, int N, int layers) {
        int total = (K / 2) * (N / 4);
        dim3 gr((total + 255) / 256, 1, layers);
        cvt_wh<<<gr, 256>>>(in, out, K, N);
    };
    wh(qkvw,    pqkvwh, D_, 3 * D_, NLAY);
    wh(aow,     paowh,  D_, D_,     NLAY);
    wh(ff1w,    pff1wh, D_, FF,     NLAY);
    wh(ff2w,    pff2wh, FF, D_,     NLAY);
    wh(gproj_w, pgpwh,  D_, D_,     1);
    cvt_h<<<(B_ * NN * D_ / 2 / 2 + 255) / 256, 256>>>(gnf, pgnfh, B_ * NN * D_ / 2);

    // ---- embeddings ----
    fill_embed<<<(B_ * L_ * D_ + 255) / 256, 256>>>(qtok, temb, ptmp);
    hgemm<0><<<dim3(D_ / 128, (B_ * NN) / 128), 256>>>(
        pgnfh, pgpwh, gproj_b, nullptr, ptmp, B_ * NN, D_, D_, 1);
    ln_kernel<<<NROWS, 256>>>(ptmp, px, pxh, elng, elnb, pos, tok);

    // ---- 6 encoder layers ----
    for (int i = 0; i < NLAY; i++) {
        hgemm<3><<<dim3((3 * D_) / 128, NROWS / 128), 256>>>(
            pxh, pqkvwh + (size_t)i * (D_ / 2) * 3 * D_,
            qkvb + (size_t)i * 3 * D_, nullptr, (float*)pqkvh,
            NROWS, 3 * D_, D_, 0);

        attn_h<<<dim3(B_ * H_, L_ / 64), 256, ATTN_SMEM>>>(
            pqkvh, pctxh, tatt, gmask);

        hgemm<1><<<dim3(D_ / 128, NROWS / 128), 256>>>(
            pctxh, paowh + (size_t)i * (D_ / 2) * D_,
            aob + (size_t)i * D_, px, ptmp, NROWS, D_, D_, 0);
        ln_kernel<<<NROWS, 256>>>(ptmp, px, pxh, ln1g + (size_t)i * D_,
                                  ln1b + (size_t)i * D_, nullptr, nullptr);

        hgemm<2><<<dim3(FF / 128, NROWS / 128), 256>>>(
            pxh, pff1wh + (size_t)i * (D_ / 2) * FF,
            ff1b + (size_t)i * FF, nullptr, (float*)pffh, NROWS, FF, D_, 0);

        hgemm<1><<<dim3(D_ / 128, NROWS / 128), 256>>>(
            pffh, pff2wh + (size_t)i * (FF / 2) * D_,
            ff2b + (size_t)i * D_, px, ptmp, NROWS, D_, FF, 0);
        ln_kernel<<<NROWS, 256>>>(ptmp, px, pxh, ln2g + (size_t)i * D_,
                                  ln2b + (size_t)i * D_, nullptr, nullptr);
    }

    // ---- output: text rows ----
    copy_out<<<(out_size + 255) / 256, 256>>>(px, (float*)d_out, out_size);
}

// round 17
// speedup vs baseline: 2.1576x; 1.0759x over previous
#include <cuda_runtime.h>
#include <cuda_fp16.h>
#include <math.h>
#include <stdint.h>

// ---------------- problem dims ----------------
constexpr int B_   = 16;
constexpr int NQ   = 32;
constexpr int NN   = 128;
constexpr int T_   = 352;
constexpr int D_   = 768;
constexpr int H_   = 8;
constexpr int NLAY = 6;
constexpr int FF   = 3072;
constexpr int L_   = NQ + NN + T_;   // 512
constexpr int TS   = NQ + NN;        // 160
constexpr int HD   = D_ / H_;        // 96
constexpr float NEGB = -1e9f;
constexpr int QKVW_ = 3 * D_ / 2;    // 1152 words per qkv row

// ---------------- device scratch ----------------
__device__ float    g_x  [B_ * L_ * D_];
__device__ float    g_tmp[B_ * L_ * D_];
__device__ uint32_t g_qkvh[B_ * L_ * QKVW_];

__device__ uint32_t g_xh  [B_ * L_ * D_ / 2];
__device__ uint32_t g_ctxh[B_ * L_ * D_ / 2];
__device__ uint32_t g_ffh [B_ * L_ * FF / 2];

__device__ uint32_t g_qkvw_h[NLAY * D_ / 2 * 3 * D_];
__device__ uint32_t g_aow_h [NLAY * D_ / 2 * D_];
__device__ uint32_t g_ff1w_h[NLAY * D_ / 2 * FF];
__device__ uint32_t g_ff2w_h[NLAY * FF / 2 * D_];
__device__ uint32_t g_gpw_h [D_ / 2 * D_];
__device__ uint32_t g_gnf_h [B_ * NN * D_ / 2];

// ---------------- helpers ----------------
__device__ __forceinline__ uint32_t pack_h2(float lo, float hi) {
    __half2 h = __floats2half2_rn(lo, hi);
    return *reinterpret_cast<uint32_t*>(&h);
}

__device__ __forceinline__ void mma_f16(float c[4], const uint32_t a[4],
                                        const uint32_t b[2]) {
    asm volatile(
        "mma.sync.aligned.m16n8k16.row.col.f32.f16.f16.f32 "
        "{%0,%1,%2,%3}, {%4,%5,%6,%7}, {%8,%9}, {%0,%1,%2,%3};"
        : "+f"(c[0]), "+f"(c[1]), "+f"(c[2]), "+f"(c[3])
        : "r"(a[0]), "r"(a[1]), "r"(a[2]), "r"(a[3]), "r"(b[0]), "r"(b[1]));
}

__device__ __forceinline__ void ldsm4(uint32_t r[4], uint32_t addr) {
    asm volatile(
        "ldmatrix.sync.aligned.m8n8.x4.shared.b16 {%0,%1,%2,%3}, [%4];"
        : "=r"(r[0]), "=r"(r[1]), "=r"(r[2]), "=r"(r[3]) : "r"(addr));
}

// ============================================================================
// FP16 GEMM. A: [M,K/2] words. B: [K/2,N] words. K-tile = 64 K-elems (32 words)
// => half the barriers of the 32-K-tile version; LDG front-batched 4+4 uint4.
// Accumulation order identical to previous version (bit-exact outputs).
// EPI: 0 = +bias fp32   1 = +bias+resid fp32   2 = gelu -> half2 packed
//      3 = +bias -> half2 packed (qkv)
// ============================================================================
constexpr int AST2 = 36;    // A smem row stride (32 words + 4 pad)
constexpr int BSTR = 136;
constexpr int HG_SMEM = (2 * 128 * AST2 + 2 * 32 * BSTR) * 4;   // 71680 B

template <int EPI>
__global__ __launch_bounds__(256, 2)
void hgemm(const uint32_t* __restrict__ A, const uint32_t* __restrict__ Bm,
           const float* __restrict__ bias, const float* __restrict__ resid,
           float* __restrict__ C, int M, int N, int K, int mapGraph)
{
    extern __shared__ uint32_t dsm[];
    uint32_t* As = dsm;                      // 2 stages of [128][AST2]
    uint32_t* Bs = dsm + 2 * 128 * AST2;     // 2 stages of [32][BSTR]

    const int tid  = threadIdx.x;
    const int br   = blockIdx.y, bc = blockIdx.x;
    const int lane = tid & 31,  wid = tid >> 5;
    const int wm = (wid >> 2) * 64;
    const int wn = (wid & 3) * 32;
    const int lq = lane >> 2;
    const int lr = lane & 3;
    const int mrow = ((lane >> 3) & 1) * 8 + (lane & 7);
    const int koff = (lane >> 4) * 4;

    float acc[4][4][4];
#pragma unroll
    for (int mt = 0; mt < 4; mt++)
#pragma unroll
        for (int nt = 0; nt < 4; nt++)
#pragma unroll
            for (int r = 0; r < 4; r++) acc[mt][nt][r] = 0.f;

    const int Kw  = K >> 1;
    const int nkt = K >> 6;                  // 64 K-elems (32 words) per tile
    uint4 pa[4], pb[4];

    // A: row = tid>>1 (two threads per row, 16 words each)
    const int ar = tid >> 1, acg = (tid & 1) * 16;
    // B: rows (tid>>5)+8j, cols (tid&31)*4 — fully coalesced
    const int br0 = tid >> 5, bcg = (tid & 31) << 2;

    auto ldA = [&](int kt) {
        const uint32_t* p = A + (size_t)(br * 128 + ar) * Kw + kt * 32 + acg;
#pragma unroll
        for (int i = 0; i < 4; i++) pa[i] = *(const uint4*)(p + 4 * i);
    };
    auto ldB = [&](int kt) {
#pragma unroll
        for (int j = 0; j < 4; j++)
            pb[j] = *(const uint4*)(Bm + (size_t)(kt * 32 + br0 + 8 * j) * N +
                                    bc * 128 + bcg);
    };
    auto stAB = [&](int buf) {
        uint32_t* a = As + buf * 128 * AST2 + ar * AST2 + acg;
#pragma unroll
        for (int i = 0; i < 4; i++) *(uint4*)(a + 4 * i) = pa[i];
        uint32_t* bgs = Bs + buf * 32 * BSTR;
#pragma unroll
        for (int j = 0; j < 4; j++)
            *(uint4*)(bgs + (br0 + 8 * j) * BSTR + bcg) = pb[j];
    };
    auto compute = [&](int buf) {
        uint32_t abase = (uint32_t)__cvta_generic_to_shared(As + buf * 128 * AST2);
        const uint32_t* Bb = Bs + buf * 32 * BSTR;
#pragma unroll
        for (int k8 = 0; k8 < 32; k8 += 8) {
            uint32_t af[4][4], bf[4][2];
#pragma unroll
            for (int mt = 0; mt < 4; mt++)
                ldsm4(af[mt],
                      abase + (uint32_t)((wm + mt * 16 + mrow) * AST2 + k8 + koff) * 4);
#pragma unroll
            for (int nt = 0; nt < 4; nt++) {
                const uint32_t* p = &Bb[(k8 + lr) * BSTR + wn + nt * 8 + lq];
                bf[nt][0] = p[0];
                bf[nt][1] = p[4 * BSTR];
            }
#pragma unroll
            for (int mt = 0; mt < 4; mt++)
#pragma unroll
                for (int nt = 0; nt < 4; nt++)
                    mma_f16(acc[mt][nt], af[mt], bf[nt]);
        }
    };

    ldA(0); ldB(0);
    stAB(0);
    __syncthreads();
    for (int kt = 0; kt < nkt; kt++) {
        int buf = kt & 1;
        bool more = (kt + 1 < nkt);
        if (more) { ldA(kt + 1); ldB(kt + 1); }
        compute(buf);
        if (more) stAB(buf ^ 1);
        __syncthreads();
    }

    // ---- epilogue ----
#pragma unroll
    for (int mt = 0; mt < 4; mt++) {
        int rbase = br * 128 + wm + mt * 16 + lq;
#pragma unroll
        for (int nt = 0; nt < 4; nt++) {
            int col = bc * 128 + wn + nt * 8 + lr * 2;
            float b0 = bias[col], b1 = bias[col + 1];
#pragma unroll
            for (int hh = 0; hh < 2; hh++) {
                int row = rbase + hh * 8;
                int orow = mapGraph ? (row / NN) * L_ + NQ + (row % NN) : row;
                float v0 = acc[mt][nt][hh * 2 + 0] + b0;
                float v1 = acc[mt][nt][hh * 2 + 1] + b1;
                if (EPI == 1) {
                    v0 += resid[(size_t)row * N + col];
                    v1 += resid[(size_t)row * N + col + 1];
                }
                if (EPI == 2) {
                    v0 = 0.5f * v0 * (1.0f + erff(v0 * 0.7071067811865475f));
                    v1 = 0.5f * v1 * (1.0f + erff(v1 * 0.7071067811865475f));
                }
                if (EPI == 2 || EPI == 3) {
                    ((uint32_t*)C)[(size_t)orow * (N >> 1) + (col >> 1)] =
                        pack_h2(v0, v1);
                } else {
                    *(float2*)(C + (size_t)orow * N + col) = make_float2(v0, v1);
                }
            }
        }
    }
}

// ============================================================================
// conversion passes
// ============================================================================
__global__ void cvt_h(const float* __restrict__ in, uint32_t* __restrict__ out,
                      int nwords)
{
    int w = (blockIdx.x * blockDim.x + threadIdx.x) * 2;
    if (w >= nwords) return;
    float4 v = *(const float4*)(in + 2 * w);
    *(uint2*)(out + w) = make_uint2(pack_h2(v.x, v.y), pack_h2(v.z, v.w));
}

__global__ void cvt_wh(const float* __restrict__ in, uint32_t* __restrict__ out,
                       int K, int N)
{
    const float* ip = in + (size_t)blockIdx.z * K * N;
    uint32_t* op = out + (size_t)blockIdx.z * (K / 2) * N;
    int idx = blockIdx.x * blockDim.x + threadIdx.x;
    int total = (K >> 1) * (N >> 2);
    if (idx >= total) return;
    int kp = idx / (N >> 2), ng = (idx % (N >> 2)) * 4;
    const float* r0 = ip + (size_t)(2 * kp) * N + ng;
    float4 a = *(const float4*)r0;
    float4 b = *(const float4*)(r0 + N);
    *(uint4*)(op + (size_t)kp * N + ng) =
        make_uint4(pack_h2(a.x, b.x), pack_h2(a.y, b.y),
                   pack_h2(a.z, b.z), pack_h2(a.w, b.w));
}

// ============================================================================
// Row LayerNorm (D=768); dual fp32 + fp16 output
// ============================================================================
__global__ __launch_bounds__(256)
void ln_kernel(const float* __restrict__ in, float* __restrict__ out,
               uint32_t* __restrict__ out_h,
               const float* __restrict__ g, const float* __restrict__ bta,
               const float* __restrict__ pos, const float* __restrict__ tok)
{
    const int row = blockIdx.x;
    const int l = row % L_;
    const int tid = threadIdx.x;
    const int lane = tid & 31, wid = tid >> 5;
    const float* ip = in + (size_t)row * D_;

    float v[3];
    float s = 0.f;
#pragma unroll
    for (int i = 0; i < 3; i++) {
        int d = tid + i * 256;
        float x = ip[d];
        if (pos) x += pos[l * D_ + d] + tok[d];
        v[i] = x;
        s += x;
    }
#pragma unroll
    for (int o = 16; o > 0; o >>= 1) s += __shfl_xor_sync(0xffffffffu, s, o);

    __shared__ float red[8];
    __shared__ float smean, sinv;
    if (lane == 0) red[wid] = s;
    __syncthreads();
    if (tid == 0) {
        float t = 0.f;
#pragma unroll
        for (int j = 0; j < 8; j++) t += red[j];
        smean = t * (1.0f / 768.0f);
    }
    __syncthreads();
    float mean = smean;

    float ss = 0.f;
#pragma unroll
    for (int i = 0; i < 3; i++) {
        float d0 = v[i] - mean;
        ss += d0 * d0;
    }
#pragma unroll
    for (int o = 16; o > 0; o >>= 1) ss += __shfl_xor_sync(0xffffffffu, ss, o);
    if (lane == 0) red[wid] = ss;
    __syncthreads();
    if (tid == 0) {
        float t = 0.f;
#pragma unroll
        for (int j = 0; j < 8; j++) t += red[j];
        sinv = rsqrtf(t * (1.0f / 768.0f) + 1e-12f);
    }
    __syncthreads();
    float inv = sinv;

    float* op = out + (size_t)row * D_;
    __half* oh = (__half*)(out_h + (size_t)row * (D_ / 2));
#pragma unroll
    for (int i = 0; i < 3; i++) {
        int d = tid + i * 256;
        float y = (v[i] - mean) * inv * g[d] + bta[d];
        op[d] = y;
        oh[d] = __float2half_rn(y);
    }
}

// ============================================================================
// FP16 attention with causal chunk skipping (proven R15 version, unchanged).
// ============================================================================
constexpr int QW3 = 72;
constexpr int VW3 = 104;
constexpr int SW3 = 520;
constexpr int ATTN_SMEM =
    (64 * QW3 + 2 * 64 * QW3 + 2 * 32 * VW3 + 64 * SW3 + 512) * 4;

__global__ __launch_bounds__(256)
void attn_h(const uint32_t* __restrict__ qkv, uint32_t* __restrict__ ctxh,
            const int* __restrict__ text_atts, const int* __restrict__ graph_mask)
{
    const int bh = blockIdx.x;
    const int b = bh / H_, h = bh % H_;
    const int qt = blockIdx.y;
    const int tid = threadIdx.x;
    const int lane = tid & 31, wid = tid >> 5;
    const int lq = lane >> 2, lr = lane & 3;

    const int nch = (qt < 3) ? 3 : (qt + 1);

    extern __shared__ uint32_t smu[];
    uint32_t* Qs = smu;
    uint32_t* Kb = Qs + 64 * QW3;
    uint32_t* Vb = Kb + 2 * 64 * QW3;
    uint32_t* Sb = Vb + 2 * 32 * VW3;
    int* keep = (int*)(Sb + 64 * SW3);

    for (int j = tid; j < L_; j += 256)
        keep[j] = (j < NQ) ? 1
                : (j < TS) ? graph_mask[b * NN + (j - NQ)]
                           : text_atts[b * T_ + (j - TS)];

    {
        const uint32_t* qbase = qkv + (size_t)(b * L_ + qt * 64) * QKVW_ + h * 48;
        int r = tid >> 2, w0 = (tid & 3) * 12;
#pragma unroll
        for (int i = 0; i < 3; i++)
            *(uint4*)&Qs[r * QW3 + w0 + 4 * i] =
                *(const uint4*)(qbase + (size_t)r * QKVW_ + w0 + 4 * i);
    }

    const int wm  = (wid >> 1) * 16;
    const int wnS = (wid & 1) * 32;
    const int wnV = (wid & 1) * 48;
    const float scale = 0.10206207261596577f;

    uint4 preK[3];
    const int kr = tid >> 2, kw0 = (tid & 3) * 12;
    auto ldK = [&](int kc) {
        const uint32_t* base =
            qkv + (size_t)(b * L_ + kc * 64) * QKVW_ + 384 + h * 48;
#pragma unroll
        for (int i = 0; i < 3; i++)
            preK[i] = *(const uint4*)(base + (size_t)kr * QKVW_ + kw0 + 4 * i);
    };
    auto stK = [&](int buf) {
        uint32_t* K = Kb + buf * 64 * QW3;
#pragma unroll
        for (int i = 0; i < 3; i++)
            *(uint4*)&K[kr * QW3 + kw0 + 4 * i] = preK[i];
    };

    uint2 preVa[3], preVb[3];
    const int vkp = tid >> 3, vcw = (tid & 7) * 6;
    auto ldV = [&](int kc) {
        const uint32_t* base =
            qkv + (size_t)(b * L_ + kc * 64) * QKVW_ + 768 + h * 48;
        const uint32_t* rA = base + (size_t)(2 * vkp) * QKVW_ + vcw;
        const uint32_t* rB = rA + QKVW_;
#pragma unroll
        for (int i = 0; i < 3; i++) {
            preVa[i] = *(const uint2*)(rA + 2 * i);
            preVb[i] = *(const uint2*)(rB + 2 * i);
        }
    };
    auto stV = [&](int buf) {
        uint32_t* V = Vb + buf * 32 * VW3;
        uint32_t o[12];
#pragma unroll
        for (int i = 0; i < 3; i++) {
            o[4 * i + 0] = __byte_perm(preVa[i].x, preVb[i].x, 0x5410);
            o[4 * i + 1] = __byte_perm(preVa[i].x, preVb[i].x, 0x7632);
            o[4 * i + 2] = __byte_perm(preVa[i].y, preVb[i].y, 0x5410);
            o[4 * i + 3] = __byte_perm(preVa[i].y, preVb[i].y, 0x7632);
        }
        uint32_t* dst = &V[vkp * VW3 + 2 * vcw];
#pragma unroll
        for (int i = 0; i < 3; i++)
            *(uint4*)(dst + 4 * i) = *(uint4*)(o + 4 * i);
    };

    // ---------------- score phase (only live chunks) ----------------
    ldK(0);
    stK(0);
    __syncthreads();
    for (int kc = 0; kc < nch; kc++) {
        if (kc + 1 < nch) ldK(kc + 1);

        const uint32_t* Ks = Kb + (kc & 1) * 64 * QW3;
        float sacc[4][4];
#pragma unroll
        for (int nt = 0; nt < 4; nt++)
#pragma unroll
            for (int r = 0; r < 4; r++) sacc[nt][r] = 0.f;

#pragma unroll
        for (int k8 = 0; k8 < 48; k8 += 8) {
            uint32_t af[4];
            const uint32_t* qp = &Qs[(wm + lq) * QW3 + k8 + lr];
            af[0] = qp[0];
            af[1] = qp[8 * QW3];
            af[2] = qp[4];
            af[3] = qp[8 * QW3 + 4];
#pragma unroll
            for (int nt = 0; nt < 4; nt++) {
                const uint32_t* kp2 = &Ks[(wnS + nt * 8 + lq) * QW3 + k8 + lr];
                uint32_t bf[2] = {kp2[0], kp2[4]};
                mma_f16(sacc[nt], af, bf);
            }
        }

        if (kc + 1 < nch) stK((kc + 1) & 1);

        float* Sf = (float*)Sb;
#pragma unroll
        for (int nt = 0; nt < 4; nt++) {
            int kg = kc * 64 + wnS + nt * 8 + 2 * lr;
            bool k0 = keep[kg] != 0, k1 = keep[kg + 1] != 0;
#pragma unroll
            for (int half = 0; half < 2; half++) {
                int qrow = wm + lq + half * 8;
                int qg = qt * 64 + qrow;
                bool qok = keep[qg] != 0;
                bool ok0 = qok && k0, ok1 = qok && k1;
                if (qg < TS) {
                    if (kg     >= TS) ok0 = false;
                    if (kg + 1 >= TS) ok1 = false;
                } else {
                    if (kg     >= TS && qg < kg)     ok0 = false;
                    if (kg + 1 >= TS && qg < kg + 1) ok1 = false;
                }
                float v0 = sacc[nt][half * 2 + 0] * scale + (ok0 ? 0.f : NEGB);
                float v1 = sacc[nt][half * 2 + 1] * scale + (ok1 ? 0.f : NEGB);
                *(float2*)&Sf[qrow * SW3 + kg] = make_float2(v0, v1);
            }
        }
        __syncthreads();
    }

    // ---- softmax over live region only; pack P as half2 key-pairs ----
    ldV(0);
    {
        const int limit = nch * 64;
        int r = tid >> 2, p = tid & 3;
        int base = p * 128;
        int cnt = limit - base;
        cnt = cnt < 0 ? 0 : (cnt > 128 ? 128 : cnt);
        float* row = (float*)Sb + r * SW3 + base;
        float m = -INFINITY;
#pragma unroll 4
        for (int k = 0; k < cnt; k++) m = fmaxf(m, row[k]);
        m = fmaxf(m, __shfl_xor_sync(0xffffffffu, m, 1));
        m = fmaxf(m, __shfl_xor_sync(0xffffffffu, m, 2));
        float sum = 0.f;
#pragma unroll 4
        for (int k = 0; k < cnt; k++) {
            float e = __expf(row[k] - m);
            row[k] = e;
            sum += e;
        }
        sum += __shfl_xor_sync(0xffffffffu, sum, 1);
        sum += __shfl_xor_sync(0xffffffffu, sum, 2);
        float inv = 1.f / sum;
        uint32_t* rowp = Sb + r * SW3 + base;
        int cntw = cnt >> 1;
#pragma unroll 4
        for (int j = 0; j < cntw; j++) {
            float e0 = row[2 * j] * inv;
            float e1 = row[2 * j + 1] * inv;
            rowp[j] = pack_h2(e0, e1);
        }
    }
    stV(0);
    __syncthreads();

    // ---------------- P @ V phase (only live chunks) ----------------
    float oacc[6][4];
#pragma unroll
    for (int nt = 0; nt < 6; nt++)
#pragma unroll
        for (int r = 0; r < 4; r++) oacc[nt][r] = 0.f;

    for (int kc = 0; kc < nch; kc++) {
        if (kc + 1 < nch) ldV(kc + 1);

        const uint32_t* Vs = Vb + (kc & 1) * 32 * VW3;
        const int pbase = (wm + lq) * SW3 + kc * 32 + (kc >> 1) * 64;
#pragma unroll
        for (int k8 = 0; k8 < 32; k8 += 8) {
            uint32_t af[4];
            const uint32_t* pp = &Sb[pbase + k8 + lr];
            af[0] = pp[0];
            af[1] = pp[8 * SW3];
            af[2] = pp[4];
            af[3] = pp[8 * SW3 + 4];
#pragma unroll
            for (int nt = 0; nt < 6; nt++) {
                const uint32_t* vp = &Vs[(k8 + lr) * VW3 + wnV + nt * 8 + lq];
                uint32_t bf[2] = {vp[0], vp[4 * VW3]};
                mma_f16(oacc[nt], af, bf);
            }
        }

        if (kc + 1 < nch) {
            stV((kc + 1) & 1);
            __syncthreads();
        }
    }

#pragma unroll
    for (int nt = 0; nt < 6; nt++) {
#pragma unroll
        for (int half = 0; half < 2; half++) {
            int qrow = qt * 64 + wm + lq + half * 8;
            int col = h * HD + wnV + nt * 8 + 2 * lr;
            ctxh[(size_t)(b * L_ + qrow) * (D_ / 2) + (col >> 1)] =
                pack_h2(oacc[nt][half * 2 + 0], oacc[nt][half * 2 + 1]);
        }
    }
}

// ============================================================================
// misc elementwise
// ============================================================================
__global__ void fill_embed(const float* __restrict__ qtok,
                           const float* __restrict__ temb,
                           float* __restrict__ out)
{
    int idx = blockIdx.x * blockDim.x + threadIdx.x;
    if (idx >= B_ * L_ * D_) return;
    int rem = idx % (L_ * D_);
    int b = idx / (L_ * D_);
    int l = rem / D_, d = rem % D_;
    if (l < NQ)
        out[idx] = qtok[l * D_ + d];
    else if (l >= TS)
        out[idx] = temb[(size_t)(b * T_ + (l - TS)) * D_ + d];
}

__global__ void copy_out(const float* __restrict__ x, float* __restrict__ out, int n)
{
    int idx = blockIdx.x * blockDim.x + threadIdx.x;
    if (idx >= n) return;
    int rem = idx % (T_ * D_);
    int b = idx / (T_ * D_);
    int t = rem / D_, d = rem % D_;
    out[idx] = x[(size_t)(b * L_ + TS + t) * D_ + d];
}

// ============================================================================
// launcher
// ============================================================================
extern "C" void kernel_launch(void* const* d_in, const int* in_sizes, int n_in,
                              void* d_out, int out_size)
{
    const float* gnf     = (const float*)d_in[0];
    const float* temb    = (const float*)d_in[1];
    const int*   tatt    = (const int*)  d_in[2];
    const int*   gmask   = (const int*)  d_in[3];
    const float* qtok    = (const float*)d_in[4];
    const float* gproj_w = (const float*)d_in[5];
    const float* gproj_b = (const float*)d_in[6];
    const float* pos     = (const float*)d_in[7];
    const float* tok     = (const float*)d_in[8];
    const float* elng    = (const float*)d_in[9];
    const float* elnb    = (const float*)d_in[10];
    const float* qkvw    = (const float*)d_in[11];
    const float* qkvb    = (const float*)d_in[12];
    const float* aow     = (const float*)d_in[13];
    const float* aob     = (const float*)d_in[14];
    const float* ln1g    = (const float*)d_in[15];
    const float* ln1b    = (const float*)d_in[16];
    const float* ff1w    = (const float*)d_in[17];
    const float* ff1b    = (const float*)d_in[18];
    const float* ff2w    = (const float*)d_in[19];
    const float* ff2b    = (const float*)d_in[20];
    const float* ln2g    = (const float*)d_in[21];
    const float* ln2b    = (const float*)d_in[22];

    float *px, *ptmp;
    uint32_t *pqkvh, *pxh, *pctxh, *pffh;
    uint32_t *pqkvwh, *paowh, *pff1wh, *pff2wh, *pgpwh, *pgnfh;
    cudaGetSymbolAddress((void**)&px,    g_x);
    cudaGetSymbolAddress((void**)&ptmp,  g_tmp);
    cudaGetSymbolAddress((void**)&pqkvh, g_qkvh);
    cudaGetSymbolAddress((void**)&pxh,   g_xh);
    cudaGetSymbolAddress((void**)&pctxh, g_ctxh);
    cudaGetSymbolAddress((void**)&pffh,  g_ffh);
    cudaGetSymbolAddress((void**)&pqkvwh, g_qkvw_h);
    cudaGetSymbolAddress((void**)&paowh,  g_aow_h);
    cudaGetSymbolAddress((void**)&pff1wh, g_ff1w_h);
    cudaGetSymbolAddress((void**)&pff2wh, g_ff2w_h);
    cudaGetSymbolAddress((void**)&pgpwh,  g_gpw_h);
    cudaGetSymbolAddress((void**)&pgnfh,  g_gnf_h);

    cudaFuncSetAttribute(attn_h, cudaFuncAttributeMaxDynamicSharedMemorySize,
                         ATTN_SMEM);
    cudaFuncSetAttribute(hgemm<0>, cudaFuncAttributeMaxDynamicSharedMemorySize, HG_SMEM);
    cudaFuncSetAttribute(hgemm<1>, cudaFuncAttributeMaxDynamicSharedMemorySize, HG_SMEM);
    cudaFuncSetAttribute(hgemm<2>, cudaFuncAttributeMaxDynamicSharedMemorySize, HG_SMEM);
    cudaFuncSetAttribute(hgemm<3>, cudaFuncAttributeMaxDynamicSharedMemorySize, HG_SMEM);

    const int NROWS = B_ * L_;   // 8192

    // ---- one-time weight packing ----
    auto wh = [](const float* in, uint32_t* out, int K, int N, int layers) {
        int total = (K / 2) * (N / 4);
        dim3 gr((total + 255) / 256, 1, layers);
        cvt_wh<<<gr, 256>>>(in, out, K, N);
    };
    wh(qkvw,    pqkvwh, D_, 3 * D_, NLAY);
    wh(aow,     paowh,  D_, D_,     NLAY);
    wh(ff1w,    pff1wh, D_, FF,     NLAY);
    wh(ff2w,    pff2wh, FF, D_,     NLAY);
    wh(gproj_w, pgpwh,  D_, D_,     1);
    cvt_h<<<(B_ * NN * D_ / 2 / 2 + 255) / 256, 256>>>(gnf, pgnfh, B_ * NN * D_ / 2);

    // ---- embeddings ----
    fill_embed<<<(B_ * L_ * D_ + 255) / 256, 256>>>(qtok, temb, ptmp);
    hgemm<0><<<dim3(D_ / 128, (B_ * NN) / 128), 256, HG_SMEM>>>(
        pgnfh, pgpwh, gproj_b, nullptr, ptmp, B_ * NN, D_, D_, 1);
    ln_kernel<<<NROWS, 256>>>(ptmp, px, pxh, elng, elnb, pos, tok);

    // ---- 6 encoder layers ----
    for (int i = 0; i < NLAY; i++) {
        hgemm<3><<<dim3((3 * D_) / 128, NROWS / 128), 256, HG_SMEM>>>(
            pxh, pqkvwh + (size_t)i * (D_ / 2) * 3 * D_,
            qkvb + (size_t)i * 3 * D_, nullptr, (float*)pqkvh,
            NROWS, 3 * D_, D_, 0);

        attn_h<<<dim3(B_ * H_, L_ / 64), 256, ATTN_SMEM>>>(
            pqkvh, pctxh, tatt, gmask);

        hgemm<1><<<dim3(D_ / 128, NROWS / 128), 256, HG_SMEM>>>(
            pctxh, paowh + (size_t)i * (D_ / 2) * D_,
            aob + (size_t)i * D_, px, ptmp, NROWS, D_, D_, 0);
        ln_kernel<<<NROWS, 256>>>(ptmp, px, pxh, ln1g + (size_t)i * D_,
                                  ln1b + (size_t)i * D_, nullptr, nullptr);

        hgemm<2><<<dim3(FF / 128, NROWS / 128), 256, HG_SMEM>>>(
            pxh, pff1wh + (size_t)i * (D_ / 2) * FF,
            ff1b + (size_t)i * FF, nullptr, (float*)pffh, NROWS, FF, D_, 0);

        hgemm<1><<<dim3(D_ / 128, NROWS / 128), 256, HG_SMEM>>>(
            pffh, pff2wh + (size_t)i * (FF / 2) * D_,
            ff2b + (size_t)i * D_, px, ptmp, NROWS, D_, FF, 0);
        ln_kernel<<<NROWS, 256>>>(ptmp, px, pxh, ln2g + (size_t)i * D_,
                                  ln2b + (size_t)i * D_, nullptr, nullptr);
    }

    // ---- output: text rows ----
    copy_out<<<(out_size + 255) / 256, 256>>>(px, (float*)d_out, out_size);
}